// round 11
// baseline (speedup 1.0000x reference)
#include <cuda_runtime.h>
#include <cuda_fp16.h>
#include <cuda_bf16.h>
#include <cstdint>

// ---------------- problem constants ----------------
#define MAXN    100000
#define MAXE    3200000
#define NFEAT   512
#define HID     64
#define NCLASS  64
#define ALPHA   0.1f
#define NITER   10
#define SCAN_BLK 1024
#define MAX_SCAN_BLOCKS 128

// ---------------- static device scratch ----------------
__device__ float    g_z0[MAXN * NCLASS];   // fp32 base prediction
__device__ __half   g_y0[MAXN * NCLASS];   // fp16 cast of z0
__device__ __half   g_ya[MAXN * NCLASS];   // fp16 scaled z ping
__device__ __half   g_yb[MAXN * NCLASS];   // fp16 scaled z pong
__device__ int      g_rowptr[MAXN + 1];
__device__ int      g_cursor[MAXN];
__device__ int      g_state[MAX_SCAN_BLOCKS];  // chained-scan states (memset / launch)
__device__ uint32_t g_edges[MAXE];         // packed: src(17b) << 15 | w_q15(15b)

// ================= mma.sync helpers (baseline sm_80+, works on sm_103) ====
__device__ __forceinline__ uint32_t smem_u32(const void* p) {
    uint32_t a;
    asm("{ .reg .u64 t; cvta.to.shared.u64 t, %1; cvt.u32.u64 %0, t; }"
        : "=r"(a) : "l"(p));
    return a;
}
__device__ __forceinline__ void ldsm_x4(uint32_t* r, uint32_t addr) {
    asm volatile("ldmatrix.sync.aligned.m8n8.x4.shared.b16 {%0,%1,%2,%3}, [%4];"
                 : "=r"(r[0]), "=r"(r[1]), "=r"(r[2]), "=r"(r[3]) : "r"(addr));
}
__device__ __forceinline__ void ldsm_x4_t(uint32_t* r, uint32_t addr) {
    asm volatile("ldmatrix.sync.aligned.m8n8.x4.trans.shared.b16 {%0,%1,%2,%3}, [%4];"
                 : "=r"(r[0]), "=r"(r[1]), "=r"(r[2]), "=r"(r[3]) : "r"(addr));
}
__device__ __forceinline__ void mma_bf16(
    float* d, const uint32_t* a, const uint32_t* b)
{
    asm volatile(
        "mma.sync.aligned.m16n8k16.row.col.f32.bf16.bf16.f32 "
        "{%0,%1,%2,%3}, {%4,%5,%6,%7}, {%8,%9}, {%0,%1,%2,%3};"
        : "+f"(d[0]), "+f"(d[1]), "+f"(d[2]), "+f"(d[3])
        : "r"(a[0]), "r"(a[1]), "r"(a[2]), "r"(a[3]), "r"(b[0]), "r"(b[1]));
}
__device__ __forceinline__ uint32_t pkbf2(float a, float b) {
    __nv_bfloat162 h = __floats2bfloat162_rn(a, b);
    return *reinterpret_cast<uint32_t*>(&h);
}

// =================================================================
// mma.sync fused GEMM: z0 = relu(x @ W1) @ W2, bf16 hi/lo 3-term split.
// =================================================================
#define GM_AHI 0
#define GM_ALO 36864
#define GM_BHI 73728
#define GM_BLO 82944
#define GM_SMEM 92160

__global__ __launch_bounds__(256) void gemm_mma(
    const float* __restrict__ X, const float* __restrict__ W1,
    const float* __restrict__ W2, float* __restrict__ Z0, int n)
{
    extern __shared__ char smc[];
    const uint32_t sb = smem_u32(smc);
    const int tid = threadIdx.x;
    const int wid = tid >> 5;
    const int l   = tid & 31;
    const int bm  = blockIdx.x * 256;
    const int wr  = wid * 32;

    const int arow = (l & 7) + ((l >> 3) & 1) * 8;
    const uint32_t akb = ((l >> 4) & 1) * 16;
    const uint32_t aoff0 = (uint32_t)(wr + arow) * 144 + akb;
    const uint32_t aoff1 = (uint32_t)(wr + 16 + arow) * 144 + akb;
    const uint32_t boff  = (uint32_t)arow * 144 + akb;

    float acc[2][8][4];
#pragma unroll
    for (int am = 0; am < 2; am++)
#pragma unroll
        for (int na = 0; na < 8; na++)
#pragma unroll
            for (int q = 0; q < 4; q++) acc[am][na][q] = 0.f;

    for (int c = 0; c < 8; c++) {
#pragma unroll
        for (int it = 0; it < 16; it++) {
            int idx = it * 256 + tid;
            int r   = idx >> 4;
            int c4  = idx & 15;
            int row = bm + r;
            float4 v = make_float4(0.f, 0.f, 0.f, 0.f);
            if (row < n)
                v = *reinterpret_cast<const float4*>(X + (size_t)row * NFEAT + c * 64 + c4 * 4);
            uint32_t h0 = pkbf2(v.x, v.y), h1 = pkbf2(v.z, v.w);
            __nv_bfloat162 bh0 = *reinterpret_cast<__nv_bfloat162*>(&h0);
            __nv_bfloat162 bh1 = *reinterpret_cast<__nv_bfloat162*>(&h1);
            float2 f0 = __bfloat1622float2(bh0);
            float2 f1 = __bfloat1622float2(bh1);
            uint32_t l0 = pkbf2(v.x - f0.x, v.y - f0.y);
            uint32_t l1 = pkbf2(v.z - f1.x, v.w - f1.y);
            uint32_t off = (uint32_t)r * 144 + c4 * 8;
            *reinterpret_cast<uint2*>(smc + GM_AHI + off) = make_uint2(h0, h1);
            *reinterpret_cast<uint2*>(smc + GM_ALO + off) = make_uint2(l0, l1);
        }
#pragma unroll
        for (int it = 0; it < 4; it++) {
            int idx = it * 256 + tid;
            int k   = idx >> 4;
            int c4  = idx & 15;
            float4 v = *reinterpret_cast<const float4*>(W1 + (size_t)(c * 64 + k) * HID + c4 * 4);
            uint32_t h0 = pkbf2(v.x, v.y), h1 = pkbf2(v.z, v.w);
            __nv_bfloat162 bh0 = *reinterpret_cast<__nv_bfloat162*>(&h0);
            __nv_bfloat162 bh1 = *reinterpret_cast<__nv_bfloat162*>(&h1);
            float2 f0 = __bfloat1622float2(bh0);
            float2 f1 = __bfloat1622float2(bh1);
            uint32_t l0 = pkbf2(v.x - f0.x, v.y - f0.y);
            uint32_t l1 = pkbf2(v.z - f1.x, v.w - f1.y);
            uint32_t off = (uint32_t)k * 144 + c4 * 8;
            *reinterpret_cast<uint2*>(smc + GM_BHI + off) = make_uint2(h0, h1);
            *reinterpret_cast<uint2*>(smc + GM_BLO + off) = make_uint2(l0, l1);
        }
        __syncthreads();

#pragma unroll
        for (int s = 0; s < 4; s++) {
            uint32_t ah0[4], ah1[4], al0[4], al1[4];
            ldsm_x4(ah0, sb + GM_AHI + aoff0 + s * 32);
            ldsm_x4(ah1, sb + GM_AHI + aoff1 + s * 32);
            ldsm_x4(al0, sb + GM_ALO + aoff0 + s * 32);
            ldsm_x4(al1, sb + GM_ALO + aoff1 + s * 32);
            uint32_t bh[8][2], bl[8][2];
#pragma unroll
            for (int p = 0; p < 4; p++) {
                uint32_t r4[4];
                ldsm_x4_t(r4, sb + GM_BHI + s * 2304 + p * 32 + boff);
                bh[2 * p][0] = r4[0]; bh[2 * p][1] = r4[1];
                bh[2 * p + 1][0] = r4[2]; bh[2 * p + 1][1] = r4[3];
                ldsm_x4_t(r4, sb + GM_BLO + s * 2304 + p * 32 + boff);
                bl[2 * p][0] = r4[0]; bl[2 * p][1] = r4[1];
                bl[2 * p + 1][0] = r4[2]; bl[2 * p + 1][1] = r4[3];
            }
#pragma unroll
            for (int na = 0; na < 8; na++) {
                mma_bf16(acc[0][na], ah0, bh[na]);
                mma_bf16(acc[1][na], ah1, bh[na]);
                mma_bf16(acc[0][na], al0, bh[na]);
                mma_bf16(acc[1][na], al1, bh[na]);
                mma_bf16(acc[0][na], ah0, bl[na]);
                mma_bf16(acc[1][na], ah1, bl[na]);
            }
        }
        __syncthreads();
    }

    // ---- phase 2 ----
    uint32_t a2h[2][4][4], a2l[2][4][4];
#pragma unroll
    for (int am = 0; am < 2; am++)
#pragma unroll
        for (int s = 0; s < 4; s++) {
            float v00 = fmaxf(acc[am][2 * s][0], 0.f);
            float v01 = fmaxf(acc[am][2 * s][1], 0.f);
            float v02 = fmaxf(acc[am][2 * s][2], 0.f);
            float v03 = fmaxf(acc[am][2 * s][3], 0.f);
            float v10 = fmaxf(acc[am][2 * s + 1][0], 0.f);
            float v11 = fmaxf(acc[am][2 * s + 1][1], 0.f);
            float v12 = fmaxf(acc[am][2 * s + 1][2], 0.f);
            float v13 = fmaxf(acc[am][2 * s + 1][3], 0.f);
            uint32_t h;
            h = pkbf2(v00, v01); a2h[am][s][0] = h;
            { __nv_bfloat162 b = *reinterpret_cast<__nv_bfloat162*>(&h); float2 f = __bfloat1622float2(b);
              a2l[am][s][0] = pkbf2(v00 - f.x, v01 - f.y); }
            h = pkbf2(v02, v03); a2h[am][s][1] = h;
            { __nv_bfloat162 b = *reinterpret_cast<__nv_bfloat162*>(&h); float2 f = __bfloat1622float2(b);
              a2l[am][s][1] = pkbf2(v02 - f.x, v03 - f.y); }
            h = pkbf2(v10, v11); a2h[am][s][2] = h;
            { __nv_bfloat162 b = *reinterpret_cast<__nv_bfloat162*>(&h); float2 f = __bfloat1622float2(b);
              a2l[am][s][2] = pkbf2(v10 - f.x, v11 - f.y); }
            h = pkbf2(v12, v13); a2h[am][s][3] = h;
            { __nv_bfloat162 b = *reinterpret_cast<__nv_bfloat162*>(&h); float2 f = __bfloat1622float2(b);
              a2l[am][s][3] = pkbf2(v12 - f.x, v13 - f.y); }
        }

#pragma unroll
    for (int am = 0; am < 2; am++)
#pragma unroll
        for (int na = 0; na < 8; na++)
#pragma unroll
            for (int q = 0; q < 4; q++) acc[am][na][q] = 0.f;

#pragma unroll
    for (int it = 0; it < 4; it++) {
        int idx = it * 256 + tid;
        int k   = idx >> 4;
        int c4  = idx & 15;
        float4 v = *reinterpret_cast<const float4*>(W2 + (size_t)k * NCLASS + c4 * 4);
        uint32_t h0 = pkbf2(v.x, v.y), h1 = pkbf2(v.z, v.w);
        __nv_bfloat162 bh0 = *reinterpret_cast<__nv_bfloat162*>(&h0);
        __nv_bfloat162 bh1 = *reinterpret_cast<__nv_bfloat162*>(&h1);
        float2 f0 = __bfloat1622float2(bh0);
        float2 f1 = __bfloat1622float2(bh1);
        uint32_t l0 = pkbf2(v.x - f0.x, v.y - f0.y);
        uint32_t l1 = pkbf2(v.z - f1.x, v.w - f1.y);
        uint32_t off = (uint32_t)k * 144 + c4 * 8;
        *reinterpret_cast<uint2*>(smc + GM_BHI + off) = make_uint2(h0, h1);
        *reinterpret_cast<uint2*>(smc + GM_BLO + off) = make_uint2(l0, l1);
    }
    __syncthreads();

#pragma unroll
    for (int s = 0; s < 4; s++) {
        uint32_t bh[8][2], bl[8][2];
#pragma unroll
        for (int p = 0; p < 4; p++) {
            uint32_t r4[4];
            ldsm_x4_t(r4, sb + GM_BHI + s * 2304 + p * 32 + boff);
            bh[2 * p][0] = r4[0]; bh[2 * p][1] = r4[1];
            bh[2 * p + 1][0] = r4[2]; bh[2 * p + 1][1] = r4[3];
            ldsm_x4_t(r4, sb + GM_BLO + s * 2304 + p * 32 + boff);
            bl[2 * p][0] = r4[0]; bl[2 * p][1] = r4[1];
            bl[2 * p + 1][0] = r4[2]; bl[2 * p + 1][1] = r4[3];
        }
#pragma unroll
        for (int na = 0; na < 8; na++) {
            mma_bf16(acc[0][na], a2h[0][s], bh[na]);
            mma_bf16(acc[1][na], a2h[1][s], bh[na]);
            mma_bf16(acc[0][na], a2l[0][s], bh[na]);
            mma_bf16(acc[1][na], a2l[1][s], bh[na]);
            mma_bf16(acc[0][na], a2h[0][s], bl[na]);
            mma_bf16(acc[1][na], a2h[1][s], bl[na]);
        }
    }

#pragma unroll
    for (int am = 0; am < 2; am++) {
        int r0 = bm + wr + am * 16 + (l >> 2);
        int col = (l & 3) * 2;
#pragma unroll
        for (int na = 0; na < 8; na++) {
            if (r0 < n)
                *reinterpret_cast<float2*>(Z0 + (size_t)r0 * NCLASS + na * 8 + col) =
                    make_float2(acc[am][na][0], acc[am][na][1]);
            if (r0 + 8 < n)
                *reinterpret_cast<float2*>(Z0 + (size_t)(r0 + 8) * NCLASS + na * 8 + col) =
                    make_float2(acc[am][na][2], acc[am][na][3]);
        }
    }
}

// =================================================================
// convert z0 (fp32) -> y0 (fp16); thread = 8 elements
// =================================================================
__global__ __launch_bounds__(256) void cvt_half(
    const float* __restrict__ z0, __half* __restrict__ y0, int total8)
{
    int i = blockIdx.x * 256 + threadIdx.x;
    if (i >= total8) return;
    const float4* p = reinterpret_cast<const float4*>(z0) + 2 * i;
    float4 a = p[0], b = p[1];
    __half2 h[4];
    h[0] = __floats2half2_rn(a.x, a.y);
    h[1] = __floats2half2_rn(a.z, a.w);
    h[2] = __floats2half2_rn(b.x, b.y);
    h[3] = __floats2half2_rn(b.z, b.w);
    reinterpret_cast<float4*>(y0)[i] = *reinterpret_cast<float4*>(h);
}

// =================================================================
// CSR construction
// =================================================================
// histogram with int4 vectorized reads (e divisible by 4 handled with tail)
__global__ __launch_bounds__(256) void hist_dst(
    const int* __restrict__ dst, int* __restrict__ cnt, int e)
{
    int i = blockIdx.x * 256 + threadIdx.x;
    int e4 = e >> 2;
    if (i < e4) {
        int4 d = __ldg(reinterpret_cast<const int4*>(dst) + i);
        atomicAdd(&cnt[d.x], 1);
        atomicAdd(&cnt[d.y], 1);
        atomicAdd(&cnt[d.z], 1);
        atomicAdd(&cnt[d.w], 1);
    }
    // tail
    int t = e4 * 4 + i;
    if (i < (e & 3) && t < e) atomicAdd(&cnt[dst[t]], 1);
}

// single-kernel chained scan: all blocks resident in one wave (nb <= 128 < 148 SMs)
// state[b] = inclusive_prefix_through_b + 1 (0 = not ready); memset before launch.
__global__ __launch_bounds__(SCAN_BLK) void scan_chained(
    const int* __restrict__ cnt, int* __restrict__ rowptr,
    int* __restrict__ cursor, int* __restrict__ state, int n, int e)
{
    __shared__ int sh[SCAN_BLK];
    __shared__ int s_prefix;
    int t = threadIdx.x;
    int b = blockIdx.x;
    int i = b * SCAN_BLK + t;
    int v = (i < n) ? cnt[i] : 0;
    sh[t] = v;
    __syncthreads();
#pragma unroll
    for (int off = 1; off < SCAN_BLK; off <<= 1) {
        int x = (t >= off) ? sh[t - off] : 0;
        __syncthreads();
        sh[t] += x;
        __syncthreads();
    }
    int incl = sh[t];
    int block_total = sh[SCAN_BLK - 1];

    if (t == 0) {
        int prefix = 0;
        if (b > 0) {
            int s;
            do { s = atomicAdd(&state[b - 1], 0); } while (s == 0);
            prefix = s - 1;
        }
        __threadfence();
        atomicExch(&state[b], prefix + block_total + 1);
        s_prefix = prefix;
    }
    __syncthreads();
    int prefix = s_prefix;

    if (i < n) {
        int r = prefix + incl - v;   // exclusive
        rowptr[i] = r;
        cursor[i] = r;
    }
    if (i == n) rowptr[n] = e;
}

// pack: src (17 bits, <<15) | weight q15 (15 bits)
__global__ __launch_bounds__(256) void build_edges(
    const int* __restrict__ src, const int* __restrict__ dst,
    const float* __restrict__ ew, int* __restrict__ cursor,
    uint32_t* __restrict__ edges, int e)
{
    int i = blockIdx.x * 256 + threadIdx.x;
    if (i < e) {
        int d = dst[i];
        int pos = atomicAdd(&cursor[d], 1);
        int q = __float2int_rn(ew[i] * 32768.0f);
        if (q > 32767) q = 32767;
        if (q < 0) q = 0;
        edges[pos] = ((uint32_t)src[i] << 15) | (uint32_t)q;
    }
}

// =================================================================
// gather (scaled fp16 pipeline): one warp per dst node.
// 4 sub-groups of 8 lanes; 2-deep unroll; packed 4B edges;
// software-pipelined edge prefetch (edge latency off critical path).
// =================================================================
__device__ __forceinline__ void load_row8_h(
    const __half* zin, uint32_t node, int c8, float* v)
{
    float4 raw = __ldg(reinterpret_cast<const float4*>(zin + (size_t)node * NCLASS) + c8);
    const __half2* h = reinterpret_cast<const __half2*>(&raw);
#pragma unroll
    for (int j = 0; j < 4; j++) {
        float2 f = __half22float2(h[j]);
        v[2 * j]     = f.x;
        v[2 * j + 1] = f.y;
    }
}
__device__ __forceinline__ void load_row8_f(
    const float* zin, int node, int c8, float* v)
{
    const float4* p = reinterpret_cast<const float4*>(zin + (size_t)node * NCLASS);
    float4 a = __ldg(p + 2 * c8);
    float4 b = __ldg(p + 2 * c8 + 1);
    v[0] = a.x; v[1] = a.y; v[2] = a.z; v[3] = a.w;
    v[4] = b.x; v[5] = b.y; v[6] = b.z; v[7] = b.w;
}

#define WQ 3.0517578125e-5f   // 1/32768

template<bool LAST>
__global__ __launch_bounds__(256) void gather_nodes(
    const uint32_t* __restrict__ edges, const int* __restrict__ rowptr,
    const __half* __restrict__ zin, const __half* __restrict__ y0,
    const float* __restrict__ z0, void* __restrict__ zout_v,
    float c1, float c0, int n)
{
    int warp = (blockIdx.x * 256 + threadIdx.x) >> 5;
    if (warp >= n) return;
    int lane = threadIdx.x & 31;
    int sub  = lane >> 3;
    int c8   = lane & 7;

    int beg = __ldg(&rowptr[warp]);
    int end = __ldg(&rowptr[warp + 1]);

    float acc[8];
#pragma unroll
    for (int j = 0; j < 8; j++) acc[j] = 0.f;

    int i = beg + sub;
    uint32_t eo0 = 0, eo1 = 0;
    if (i < end)     eo0 = __ldg(&edges[i]);
    if (i + 4 < end) eo1 = __ldg(&edges[i + 4]);

    for (; i + 4 < end; i += 8) {
        // prefetch next iteration's edges (predicated)
        int j0 = i + 8, j1 = i + 12;
        uint32_t f0 = 0, f1 = 0;
        if (j0 < end) f0 = __ldg(&edges[j0]);
        if (j1 < end) f1 = __ldg(&edges[j1]);

        float v0[8], v1[8];
        load_row8_h(zin, eo0 >> 15, c8, v0);
        load_row8_h(zin, eo1 >> 15, c8, v1);
        float w0 = (float)(eo0 & 0x7FFFu) * WQ;
        float w1 = (float)(eo1 & 0x7FFFu) * WQ;
#pragma unroll
        for (int j = 0; j < 8; j++) acc[j] = fmaf(w0, v0[j], acc[j]);
#pragma unroll
        for (int j = 0; j < 8; j++) acc[j] = fmaf(w1, v1[j], acc[j]);

        eo0 = f0; eo1 = f1;
    }
    // tail: at most one edge left for this sub-group (held in eo0)
    if (i < end) {
        float v0[8];
        load_row8_h(zin, eo0 >> 15, c8, v0);
        float w0 = (float)(eo0 & 0x7FFFu) * WQ;
#pragma unroll
        for (int j = 0; j < 8; j++) acc[j] = fmaf(w0, v0[j], acc[j]);
    }

    const unsigned FULL = 0xFFFFFFFFu;
#pragma unroll
    for (int j = 0; j < 8; j++) {
        acc[j] += __shfl_xor_sync(FULL, acc[j], 8);
        acc[j] += __shfl_xor_sync(FULL, acc[j], 16);
    }

    float z0v[8];
    if (LAST) load_row8_f(z0, warp, c8, z0v);
    else      load_row8_h(y0, (uint32_t)warp, c8, z0v);
    float o[8];
#pragma unroll
    for (int j = 0; j < 8; j++) o[j] = fmaf(c0, z0v[j], c1 * acc[j]);

    if (!LAST) {
        if (sub == 0) {
            __half2 h[4];
#pragma unroll
            for (int j = 0; j < 4; j++)
                h[j] = __floats2half2_rn(o[2 * j], o[2 * j + 1]);
            __half* zo = (__half*)zout_v;
            *(reinterpret_cast<float4*>(zo + (size_t)warp * NCLASS) + c8) =
                *reinterpret_cast<float4*>(h);
        }
    } else {
        float m = o[0];
#pragma unroll
        for (int j = 1; j < 8; j++) m = fmaxf(m, o[j]);
#pragma unroll
        for (int off = 1; off < 8; off <<= 1)
            m = fmaxf(m, __shfl_xor_sync(FULL, m, off));
        float s = 0.f;
#pragma unroll
        for (int j = 0; j < 8; j++) s += __expf(o[j] - m);
#pragma unroll
        for (int off = 1; off < 8; off <<= 1)
            s += __shfl_xor_sync(FULL, s, off);
        float l = m + __logf(s);
        if (sub == 0) {
            float* zo = (float*)zout_v;
            float4 r0 = make_float4(o[0] - l, o[1] - l, o[2] - l, o[3] - l);
            float4 r1 = make_float4(o[4] - l, o[5] - l, o[6] - l, o[7] - l);
            float4* p = reinterpret_cast<float4*>(zo + (size_t)warp * NCLASS);
            p[2 * c8]     = r0;
            p[2 * c8 + 1] = r1;
        }
    }
}

// =================================================================
// launch
// =================================================================
extern "C" void kernel_launch(void* const* d_in, const int* in_sizes, int n_in,
                              void* d_out, int out_size)
{
    const float* x   = (const float*)d_in[0];
    const int*   ei  = (const int*)  d_in[1];
    const float* ew  = (const float*)d_in[2];
    const float* W1  = (const float*)d_in[3];
    const float* W2  = (const float*)d_in[4];
    float*       out = (float*)d_out;

    const int n = in_sizes[0] / NFEAT;
    const int e = in_sizes[2];
    const int* src = ei;
    const int* dst = ei + e;

    float*    z0  = nullptr; cudaGetSymbolAddress((void**)&z0,  g_z0);
    __half*   y0  = nullptr; cudaGetSymbolAddress((void**)&y0,  g_y0);
    __half*   ya  = nullptr; cudaGetSymbolAddress((void**)&ya,  g_ya);
    __half*   yb  = nullptr; cudaGetSymbolAddress((void**)&yb,  g_yb);
    int*      rp  = nullptr; cudaGetSymbolAddress((void**)&rp,  g_rowptr);
    int*      cur = nullptr; cudaGetSymbolAddress((void**)&cur, g_cursor);
    int*      st  = nullptr; cudaGetSymbolAddress((void**)&st,  g_state);
    uint32_t* edg = nullptr; cudaGetSymbolAddress((void**)&edg, g_edges);

    static cudaStream_t sG = nullptr;
    static cudaEvent_t  evF = nullptr, evG = nullptr;
    if (sG == nullptr) {
        cudaStreamCreateWithFlags(&sG, cudaStreamNonBlocking);
        cudaEventCreateWithFlags(&evF, cudaEventDisableTiming);
        cudaEventCreateWithFlags(&evG, cudaEventDisableTiming);
        cudaFuncSetAttribute(gemm_mma,
            cudaFuncAttributeMaxDynamicSharedMemorySize, GM_SMEM);
    }

    // ---- fork: tensor-core GEMM + fp16 cast on side stream ----
    cudaEventRecord(evF, 0);
    cudaStreamWaitEvent(sG, evF, 0);
    gemm_mma<<<(n + 255) / 256, 256, GM_SMEM, sG>>>(x, W1, W2, z0, n);
    const int total8 = n * NCLASS / 8;
    cvt_half<<<(total8 + 255) / 256, 256, 0, sG>>>(z0, y0, total8);
    cudaEventRecord(evG, sG);

    // ---- CSR build on capture stream ----
    cudaMemsetAsync(cur, 0, (size_t)n * sizeof(int), 0);
    cudaMemsetAsync(st, 0, MAX_SCAN_BLOCKS * sizeof(int), 0);
    hist_dst<<<(e / 4 + 255) / 256, 256>>>(dst, cur, e);
    int nb = (n + SCAN_BLK - 1) / SCAN_BLK;
    scan_chained<<<nb, SCAN_BLK>>>(cur, rp, cur, st, n, e);
    build_edges<<<(e + 255) / 256, 256>>>(src, dst, ew, cur, edg, e);

    // ---- join ----
    cudaStreamWaitEvent(0, evG, 0);

    // ---- APPNP, scaled-fp16 pipeline ----
    // y_t = z_t / 16^t (exact power-of-two scaling)
    const float S = 16.0f;
    const int gblocks = (n * 32 + 255) / 256;

    // iter 0: y0 -> y1 (ya)
    gather_nodes<false><<<gblocks, 256>>>(
        edg, rp, y0, y0, z0, ya, 1.0f / S, ALPHA / S, n);

    // iters 1..8: y_t -> y_{t+1}   (t=8 output lands in bufs[0]=ya)
    __half* bufs[2] = { ya, yb };
    float pw = S * S;
    for (int t = 1; t <= 8; t++) {
        __half* zin  = bufs[(t + 1) & 1];
        __half* zout = bufs[t & 1];
        gather_nodes<false><<<gblocks, 256>>>(
            edg, rp, zin, y0, z0, zout, 1.0f / S, ALPHA / pw, n);
        pw *= S;
    }

    // iter 9 (final): input y9 = bufs[0], fp32 z0 injection, fused log_softmax
    float S9 = 1.0f;
    for (int k = 0; k < 9; k++) S9 *= S;
    gather_nodes<true><<<gblocks, 256>>>(
        edg, rp, bufs[0], y0, z0, out, S9, ALPHA, n);
}

// round 12
// speedup vs baseline: 1.1248x; 1.1248x over previous
#include <cuda_runtime.h>
#include <cuda_fp16.h>
#include <cuda_bf16.h>
#include <cstdint>

// ---------------- problem constants ----------------
#define MAXN    100000
#define MAXE    3200000
#define NFEAT   512
#define HID     64
#define NCLASS  64
#define ALPHA   0.1f
#define NITER   10
#define SCAN_BLK 1024

// ---------------- static device scratch ----------------
__device__ float    g_z0[MAXN * NCLASS];   // fp32 base prediction
__device__ __half   g_y0[MAXN * NCLASS];   // fp16 cast of z0
__device__ __half   g_ya[MAXN * NCLASS];   // fp16 scaled z ping
__device__ __half   g_yb[MAXN * NCLASS];   // fp16 scaled z pong
__device__ int      g_rowptr[MAXN + 1];
__device__ int      g_cursor[MAXN];
__device__ int      g_bsums[128];
__device__ uint32_t g_edges[MAXE];         // packed: src(17b) << 15 | w_q15(15b)

// ================= mma.sync helpers (baseline sm_80+, works on sm_103) ====
__device__ __forceinline__ uint32_t smem_u32(const void* p) {
    uint32_t a;
    asm("{ .reg .u64 t; cvta.to.shared.u64 t, %1; cvt.u32.u64 %0, t; }"
        : "=r"(a) : "l"(p));
    return a;
}
__device__ __forceinline__ void ldsm_x4(uint32_t* r, uint32_t addr) {
    asm volatile("ldmatrix.sync.aligned.m8n8.x4.shared.b16 {%0,%1,%2,%3}, [%4];"
                 : "=r"(r[0]), "=r"(r[1]), "=r"(r[2]), "=r"(r[3]) : "r"(addr));
}
__device__ __forceinline__ void ldsm_x4_t(uint32_t* r, uint32_t addr) {
    asm volatile("ldmatrix.sync.aligned.m8n8.x4.trans.shared.b16 {%0,%1,%2,%3}, [%4];"
                 : "=r"(r[0]), "=r"(r[1]), "=r"(r[2]), "=r"(r[3]) : "r"(addr));
}
__device__ __forceinline__ void mma_bf16(
    float* d, const uint32_t* a, const uint32_t* b)
{
    asm volatile(
        "mma.sync.aligned.m16n8k16.row.col.f32.bf16.bf16.f32 "
        "{%0,%1,%2,%3}, {%4,%5,%6,%7}, {%8,%9}, {%0,%1,%2,%3};"
        : "+f"(d[0]), "+f"(d[1]), "+f"(d[2]), "+f"(d[3])
        : "r"(a[0]), "r"(a[1]), "r"(a[2]), "r"(a[3]), "r"(b[0]), "r"(b[1]));
}
__device__ __forceinline__ uint32_t pkbf2(float a, float b) {
    __nv_bfloat162 h = __floats2bfloat162_rn(a, b);
    return *reinterpret_cast<uint32_t*>(&h);
}

// =================================================================
// mma.sync fused GEMM: z0 = relu(x @ W1) @ W2, bf16 hi/lo 3-term split.
// Epilogue also emits y0 = fp16(z0) (fused cvt).
// =================================================================
#define GM_AHI 0
#define GM_ALO 36864
#define GM_BHI 73728
#define GM_BLO 82944
#define GM_SMEM 92160

__global__ __launch_bounds__(256) void gemm_mma(
    const float* __restrict__ X, const float* __restrict__ W1,
    const float* __restrict__ W2, float* __restrict__ Z0,
    __half* __restrict__ Y0, int n)
{
    extern __shared__ char smc[];
    const uint32_t sb = smem_u32(smc);
    const int tid = threadIdx.x;
    const int wid = tid >> 5;
    const int l   = tid & 31;
    const int bm  = blockIdx.x * 256;
    const int wr  = wid * 32;

    const int arow = (l & 7) + ((l >> 3) & 1) * 8;
    const uint32_t akb = ((l >> 4) & 1) * 16;
    const uint32_t aoff0 = (uint32_t)(wr + arow) * 144 + akb;
    const uint32_t aoff1 = (uint32_t)(wr + 16 + arow) * 144 + akb;
    const uint32_t boff  = (uint32_t)arow * 144 + akb;

    float acc[2][8][4];
#pragma unroll
    for (int am = 0; am < 2; am++)
#pragma unroll
        for (int na = 0; na < 8; na++)
#pragma unroll
            for (int q = 0; q < 4; q++) acc[am][na][q] = 0.f;

    for (int c = 0; c < 8; c++) {
#pragma unroll
        for (int it = 0; it < 16; it++) {
            int idx = it * 256 + tid;
            int r   = idx >> 4;
            int c4  = idx & 15;
            int row = bm + r;
            float4 v = make_float4(0.f, 0.f, 0.f, 0.f);
            if (row < n)
                v = *reinterpret_cast<const float4*>(X + (size_t)row * NFEAT + c * 64 + c4 * 4);
            uint32_t h0 = pkbf2(v.x, v.y), h1 = pkbf2(v.z, v.w);
            __nv_bfloat162 bh0 = *reinterpret_cast<__nv_bfloat162*>(&h0);
            __nv_bfloat162 bh1 = *reinterpret_cast<__nv_bfloat162*>(&h1);
            float2 f0 = __bfloat1622float2(bh0);
            float2 f1 = __bfloat1622float2(bh1);
            uint32_t l0 = pkbf2(v.x - f0.x, v.y - f0.y);
            uint32_t l1 = pkbf2(v.z - f1.x, v.w - f1.y);
            uint32_t off = (uint32_t)r * 144 + c4 * 8;
            *reinterpret_cast<uint2*>(smc + GM_AHI + off) = make_uint2(h0, h1);
            *reinterpret_cast<uint2*>(smc + GM_ALO + off) = make_uint2(l0, l1);
        }
#pragma unroll
        for (int it = 0; it < 4; it++) {
            int idx = it * 256 + tid;
            int k   = idx >> 4;
            int c4  = idx & 15;
            float4 v = *reinterpret_cast<const float4*>(W1 + (size_t)(c * 64 + k) * HID + c4 * 4);
            uint32_t h0 = pkbf2(v.x, v.y), h1 = pkbf2(v.z, v.w);
            __nv_bfloat162 bh0 = *reinterpret_cast<__nv_bfloat162*>(&h0);
            __nv_bfloat162 bh1 = *reinterpret_cast<__nv_bfloat162*>(&h1);
            float2 f0 = __bfloat1622float2(bh0);
            float2 f1 = __bfloat1622float2(bh1);
            uint32_t l0 = pkbf2(v.x - f0.x, v.y - f0.y);
            uint32_t l1 = pkbf2(v.z - f1.x, v.w - f1.y);
            uint32_t off = (uint32_t)k * 144 + c4 * 8;
            *reinterpret_cast<uint2*>(smc + GM_BHI + off) = make_uint2(h0, h1);
            *reinterpret_cast<uint2*>(smc + GM_BLO + off) = make_uint2(l0, l1);
        }
        __syncthreads();

#pragma unroll
        for (int s = 0; s < 4; s++) {
            uint32_t ah0[4], ah1[4], al0[4], al1[4];
            ldsm_x4(ah0, sb + GM_AHI + aoff0 + s * 32);
            ldsm_x4(ah1, sb + GM_AHI + aoff1 + s * 32);
            ldsm_x4(al0, sb + GM_ALO + aoff0 + s * 32);
            ldsm_x4(al1, sb + GM_ALO + aoff1 + s * 32);
            uint32_t bh[8][2], bl[8][2];
#pragma unroll
            for (int p = 0; p < 4; p++) {
                uint32_t r4[4];
                ldsm_x4_t(r4, sb + GM_BHI + s * 2304 + p * 32 + boff);
                bh[2 * p][0] = r4[0]; bh[2 * p][1] = r4[1];
                bh[2 * p + 1][0] = r4[2]; bh[2 * p + 1][1] = r4[3];
                ldsm_x4_t(r4, sb + GM_BLO + s * 2304 + p * 32 + boff);
                bl[2 * p][0] = r4[0]; bl[2 * p][1] = r4[1];
                bl[2 * p + 1][0] = r4[2]; bl[2 * p + 1][1] = r4[3];
            }
#pragma unroll
            for (int na = 0; na < 8; na++) {
                mma_bf16(acc[0][na], ah0, bh[na]);
                mma_bf16(acc[1][na], ah1, bh[na]);
                mma_bf16(acc[0][na], al0, bh[na]);
                mma_bf16(acc[1][na], al1, bh[na]);
                mma_bf16(acc[0][na], ah0, bl[na]);
                mma_bf16(acc[1][na], ah1, bl[na]);
            }
        }
        __syncthreads();
    }

    // ---- phase 2 ----
    uint32_t a2h[2][4][4], a2l[2][4][4];
#pragma unroll
    for (int am = 0; am < 2; am++)
#pragma unroll
        for (int s = 0; s < 4; s++) {
            float v00 = fmaxf(acc[am][2 * s][0], 0.f);
            float v01 = fmaxf(acc[am][2 * s][1], 0.f);
            float v02 = fmaxf(acc[am][2 * s][2], 0.f);
            float v03 = fmaxf(acc[am][2 * s][3], 0.f);
            float v10 = fmaxf(acc[am][2 * s + 1][0], 0.f);
            float v11 = fmaxf(acc[am][2 * s + 1][1], 0.f);
            float v12 = fmaxf(acc[am][2 * s + 1][2], 0.f);
            float v13 = fmaxf(acc[am][2 * s + 1][3], 0.f);
            uint32_t h;
            h = pkbf2(v00, v01); a2h[am][s][0] = h;
            { __nv_bfloat162 b = *reinterpret_cast<__nv_bfloat162*>(&h); float2 f = __bfloat1622float2(b);
              a2l[am][s][0] = pkbf2(v00 - f.x, v01 - f.y); }
            h = pkbf2(v02, v03); a2h[am][s][1] = h;
            { __nv_bfloat162 b = *reinterpret_cast<__nv_bfloat162*>(&h); float2 f = __bfloat1622float2(b);
              a2l[am][s][1] = pkbf2(v02 - f.x, v03 - f.y); }
            h = pkbf2(v10, v11); a2h[am][s][2] = h;
            { __nv_bfloat162 b = *reinterpret_cast<__nv_bfloat162*>(&h); float2 f = __bfloat1622float2(b);
              a2l[am][s][2] = pkbf2(v10 - f.x, v11 - f.y); }
            h = pkbf2(v12, v13); a2h[am][s][3] = h;
            { __nv_bfloat162 b = *reinterpret_cast<__nv_bfloat162*>(&h); float2 f = __bfloat1622float2(b);
              a2l[am][s][3] = pkbf2(v12 - f.x, v13 - f.y); }
        }

#pragma unroll
    for (int am = 0; am < 2; am++)
#pragma unroll
        for (int na = 0; na < 8; na++)
#pragma unroll
            for (int q = 0; q < 4; q++) acc[am][na][q] = 0.f;

#pragma unroll
    for (int it = 0; it < 4; it++) {
        int idx = it * 256 + tid;
        int k   = idx >> 4;
        int c4  = idx & 15;
        float4 v = *reinterpret_cast<const float4*>(W2 + (size_t)k * NCLASS + c4 * 4);
        uint32_t h0 = pkbf2(v.x, v.y), h1 = pkbf2(v.z, v.w);
        __nv_bfloat162 bh0 = *reinterpret_cast<__nv_bfloat162*>(&h0);
        __nv_bfloat162 bh1 = *reinterpret_cast<__nv_bfloat162*>(&h1);
        float2 f0 = __bfloat1622float2(bh0);
        float2 f1 = __bfloat1622float2(bh1);
        uint32_t l0 = pkbf2(v.x - f0.x, v.y - f0.y);
        uint32_t l1 = pkbf2(v.z - f1.x, v.w - f1.y);
        uint32_t off = (uint32_t)k * 144 + c4 * 8;
        *reinterpret_cast<uint2*>(smc + GM_BHI + off) = make_uint2(h0, h1);
        *reinterpret_cast<uint2*>(smc + GM_BLO + off) = make_uint2(l0, l1);
    }
    __syncthreads();

#pragma unroll
    for (int s = 0; s < 4; s++) {
        uint32_t bh[8][2], bl[8][2];
#pragma unroll
        for (int p = 0; p < 4; p++) {
            uint32_t r4[4];
            ldsm_x4_t(r4, sb + GM_BHI + s * 2304 + p * 32 + boff);
            bh[2 * p][0] = r4[0]; bh[2 * p][1] = r4[1];
            bh[2 * p + 1][0] = r4[2]; bh[2 * p + 1][1] = r4[3];
            ldsm_x4_t(r4, sb + GM_BLO + s * 2304 + p * 32 + boff);
            bl[2 * p][0] = r4[0]; bl[2 * p][1] = r4[1];
            bl[2 * p + 1][0] = r4[2]; bl[2 * p + 1][1] = r4[3];
        }
#pragma unroll
        for (int na = 0; na < 8; na++) {
            mma_bf16(acc[0][na], a2h[0][s], bh[na]);
            mma_bf16(acc[1][na], a2h[1][s], bh[na]);
            mma_bf16(acc[0][na], a2l[0][s], bh[na]);
            mma_bf16(acc[1][na], a2l[1][s], bh[na]);
            mma_bf16(acc[0][na], a2h[0][s], bl[na]);
            mma_bf16(acc[1][na], a2h[1][s], bl[na]);
        }
    }

    // store z0 (fp32) + y0 (fp16, fused cast)
#pragma unroll
    for (int am = 0; am < 2; am++) {
        int r0 = bm + wr + am * 16 + (l >> 2);
        int col = (l & 3) * 2;
#pragma unroll
        for (int na = 0; na < 8; na++) {
            if (r0 < n) {
                *reinterpret_cast<float2*>(Z0 + (size_t)r0 * NCLASS + na * 8 + col) =
                    make_float2(acc[am][na][0], acc[am][na][1]);
                __half2 hh = __floats2half2_rn(acc[am][na][0], acc[am][na][1]);
                *reinterpret_cast<__half2*>(Y0 + (size_t)r0 * NCLASS + na * 8 + col) = hh;
            }
            if (r0 + 8 < n) {
                *reinterpret_cast<float2*>(Z0 + (size_t)(r0 + 8) * NCLASS + na * 8 + col) =
                    make_float2(acc[am][na][2], acc[am][na][3]);
                __half2 hh = __floats2half2_rn(acc[am][na][2], acc[am][na][3]);
                *reinterpret_cast<__half2*>(Y0 + (size_t)(r0 + 8) * NCLASS + na * 8 + col) = hh;
            }
        }
    }
}

// =================================================================
// CSR construction (3-kernel scan — measured ~12us, chained scan was 81us)
// =================================================================
__global__ __launch_bounds__(256) void hist_dst(
    const int* __restrict__ dst, int* __restrict__ cnt, int e)
{
    int i = blockIdx.x * 256 + threadIdx.x;
    int e4 = e >> 2;
    if (i < e4) {
        int4 d = __ldg(reinterpret_cast<const int4*>(dst) + i);
        atomicAdd(&cnt[d.x], 1);
        atomicAdd(&cnt[d.y], 1);
        atomicAdd(&cnt[d.z], 1);
        atomicAdd(&cnt[d.w], 1);
    }
    int t = e4 * 4 + i;
    if (i < (e & 3) && t < e) atomicAdd(&cnt[dst[t]], 1);
}

__global__ __launch_bounds__(SCAN_BLK) void scan1(
    const int* __restrict__ cnt, int* __restrict__ rowptr,
    int* __restrict__ bsums, int n)
{
    __shared__ int sh[SCAN_BLK];
    int t = threadIdx.x;
    int i = blockIdx.x * SCAN_BLK + t;
    int v = (i < n) ? cnt[i] : 0;
    sh[t] = v;
    __syncthreads();
#pragma unroll
    for (int off = 1; off < SCAN_BLK; off <<= 1) {
        int x = (t >= off) ? sh[t - off] : 0;
        __syncthreads();
        sh[t] += x;
        __syncthreads();
    }
    int incl = sh[t];
    if (i < n) rowptr[i] = incl - v;
    if (t == SCAN_BLK - 1) bsums[blockIdx.x] = incl;
}

__global__ __launch_bounds__(128) void scan2(int* __restrict__ bsums, int nb)
{
    __shared__ int sh[128];
    int t = threadIdx.x;
    int v = (t < nb) ? bsums[t] : 0;
    sh[t] = v;
    __syncthreads();
#pragma unroll
    for (int off = 1; off < 128; off <<= 1) {
        int x = (t >= off) ? sh[t - off] : 0;
        __syncthreads();
        sh[t] += x;
        __syncthreads();
    }
    if (t < nb) bsums[t] = sh[t] - v;
}

__global__ __launch_bounds__(256) void scan3(
    int* __restrict__ rowptr, int* __restrict__ cursor,
    const int* __restrict__ bsums, int n, int e)
{
    int i = blockIdx.x * 256 + threadIdx.x;
    if (i < n) {
        int v = rowptr[i] + bsums[i >> 10];
        rowptr[i] = v;
        cursor[i] = v;
    }
    if (i == n) rowptr[n] = e;
}

// pack: src (17 bits, <<15) | weight q15 (15 bits)
__global__ __launch_bounds__(256) void build_edges(
    const int* __restrict__ src, const int* __restrict__ dst,
    const float* __restrict__ ew, int* __restrict__ cursor,
    uint32_t* __restrict__ edges, int e)
{
    int i = blockIdx.x * 256 + threadIdx.x;
    if (i < e) {
        int d = dst[i];
        int pos = atomicAdd(&cursor[d], 1);
        int q = __float2int_rn(ew[i] * 32768.0f);
        if (q > 32767) q = 32767;
        if (q < 0) q = 0;
        edges[pos] = ((uint32_t)src[i] << 15) | (uint32_t)q;
    }
}

// =================================================================
// gather (scaled fp16 pipeline): one warp per dst node.
// 4 sub-groups of 8 lanes; 2-deep unroll; packed 4B edges.
// (round-10 proven config — no prefetch, no deep unroll)
// =================================================================
__device__ __forceinline__ void load_row8_h(
    const __half* zin, uint32_t node, int c8, float* v)
{
    float4 raw = __ldg(reinterpret_cast<const float4*>(zin + (size_t)node * NCLASS) + c8);
    const __half2* h = reinterpret_cast<const __half2*>(&raw);
#pragma unroll
    for (int j = 0; j < 4; j++) {
        float2 f = __half22float2(h[j]);
        v[2 * j]     = f.x;
        v[2 * j + 1] = f.y;
    }
}
__device__ __forceinline__ void load_row8_f(
    const float* zin, int node, int c8, float* v)
{
    const float4* p = reinterpret_cast<const float4*>(zin + (size_t)node * NCLASS);
    float4 a = __ldg(p + 2 * c8);
    float4 b = __ldg(p + 2 * c8 + 1);
    v[0] = a.x; v[1] = a.y; v[2] = a.z; v[3] = a.w;
    v[4] = b.x; v[5] = b.y; v[6] = b.z; v[7] = b.w;
}

#define WQ 3.0517578125e-5f   // 1/32768

template<bool LAST>
__global__ __launch_bounds__(256) void gather_nodes(
    const uint32_t* __restrict__ edges, const int* __restrict__ rowptr,
    const __half* __restrict__ zin, const __half* __restrict__ y0,
    const float* __restrict__ z0, void* __restrict__ zout_v,
    float c1, float c0, int n)
{
    int warp = (blockIdx.x * 256 + threadIdx.x) >> 5;
    if (warp >= n) return;
    int lane = threadIdx.x & 31;
    int sub  = lane >> 3;
    int c8   = lane & 7;

    int beg = __ldg(&rowptr[warp]);
    int end = __ldg(&rowptr[warp + 1]);

    float acc[8];
#pragma unroll
    for (int j = 0; j < 8; j++) acc[j] = 0.f;

    int i = beg + sub;
    for (; i + 4 < end; i += 8) {
        uint32_t e0 = __ldg(&edges[i]);
        uint32_t e1 = __ldg(&edges[i + 4]);
        float v0[8], v1[8];
        load_row8_h(zin, e0 >> 15, c8, v0);
        load_row8_h(zin, e1 >> 15, c8, v1);
        float w0 = (float)(e0 & 0x7FFFu) * WQ;
        float w1 = (float)(e1 & 0x7FFFu) * WQ;
#pragma unroll
        for (int j = 0; j < 8; j++) acc[j] = fmaf(w0, v0[j], acc[j]);
#pragma unroll
        for (int j = 0; j < 8; j++) acc[j] = fmaf(w1, v1[j], acc[j]);
    }
    for (; i < end; i += 4) {
        uint32_t e0 = __ldg(&edges[i]);
        float v0[8];
        load_row8_h(zin, e0 >> 15, c8, v0);
        float w0 = (float)(e0 & 0x7FFFu) * WQ;
#pragma unroll
        for (int j = 0; j < 8; j++) acc[j] = fmaf(w0, v0[j], acc[j]);
    }

    const unsigned FULL = 0xFFFFFFFFu;
#pragma unroll
    for (int j = 0; j < 8; j++) {
        acc[j] += __shfl_xor_sync(FULL, acc[j], 8);
        acc[j] += __shfl_xor_sync(FULL, acc[j], 16);
    }

    float z0v[8];
    if (LAST) load_row8_f(z0, warp, c8, z0v);
    else      load_row8_h(y0, (uint32_t)warp, c8, z0v);
    float o[8];
#pragma unroll
    for (int j = 0; j < 8; j++) o[j] = fmaf(c0, z0v[j], c1 * acc[j]);

    if (!LAST) {
        if (sub == 0) {
            __half2 h[4];
#pragma unroll
            for (int j = 0; j < 4; j++)
                h[j] = __floats2half2_rn(o[2 * j], o[2 * j + 1]);
            __half* zo = (__half*)zout_v;
            *(reinterpret_cast<float4*>(zo + (size_t)warp * NCLASS) + c8) =
                *reinterpret_cast<float4*>(h);
        }
    } else {
        float m = o[0];
#pragma unroll
        for (int j = 1; j < 8; j++) m = fmaxf(m, o[j]);
#pragma unroll
        for (int off = 1; off < 8; off <<= 1)
            m = fmaxf(m, __shfl_xor_sync(FULL, m, off));
        float s = 0.f;
#pragma unroll
        for (int j = 0; j < 8; j++) s += __expf(o[j] - m);
#pragma unroll
        for (int off = 1; off < 8; off <<= 1)
            s += __shfl_xor_sync(FULL, s, off);
        float l = m + __logf(s);
        if (sub == 0) {
            float* zo = (float*)zout_v;
            float4 r0 = make_float4(o[0] - l, o[1] - l, o[2] - l, o[3] - l);
            float4 r1 = make_float4(o[4] - l, o[5] - l, o[6] - l, o[7] - l);
            float4* p = reinterpret_cast<float4*>(zo + (size_t)warp * NCLASS);
            p[2 * c8]     = r0;
            p[2 * c8 + 1] = r1;
        }
    }
}

// =================================================================
// launch
// =================================================================
extern "C" void kernel_launch(void* const* d_in, const int* in_sizes, int n_in,
                              void* d_out, int out_size)
{
    const float* x   = (const float*)d_in[0];
    const int*   ei  = (const int*)  d_in[1];
    const float* ew  = (const float*)d_in[2];
    const float* W1  = (const float*)d_in[3];
    const float* W2  = (const float*)d_in[4];
    float*       out = (float*)d_out;

    const int n = in_sizes[0] / NFEAT;
    const int e = in_sizes[2];
    const int* src = ei;
    const int* dst = ei + e;

    float*    z0  = nullptr; cudaGetSymbolAddress((void**)&z0,  g_z0);
    __half*   y0  = nullptr; cudaGetSymbolAddress((void**)&y0,  g_y0);
    __half*   ya  = nullptr; cudaGetSymbolAddress((void**)&ya,  g_ya);
    __half*   yb  = nullptr; cudaGetSymbolAddress((void**)&yb,  g_yb);
    int*      rp  = nullptr; cudaGetSymbolAddress((void**)&rp,  g_rowptr);
    int*      cur = nullptr; cudaGetSymbolAddress((void**)&cur, g_cursor);
    int*      bs  = nullptr; cudaGetSymbolAddress((void**)&bs,  g_bsums);
    uint32_t* edg = nullptr; cudaGetSymbolAddress((void**)&edg, g_edges);

    static cudaStream_t sG = nullptr;
    static cudaEvent_t  evF = nullptr, evG = nullptr;
    if (sG == nullptr) {
        cudaStreamCreateWithFlags(&sG, cudaStreamNonBlocking);
        cudaEventCreateWithFlags(&evF, cudaEventDisableTiming);
        cudaEventCreateWithFlags(&evG, cudaEventDisableTiming);
        cudaFuncSetAttribute(gemm_mma,
            cudaFuncAttributeMaxDynamicSharedMemorySize, GM_SMEM);
    }

    // ---- fork: tensor-core GEMM (with fused fp16 cast) on side stream ----
    cudaEventRecord(evF, 0);
    cudaStreamWaitEvent(sG, evF, 0);
    gemm_mma<<<(n + 255) / 256, 256, GM_SMEM, sG>>>(x, W1, W2, z0, y0, n);
    cudaEventRecord(evG, sG);

    // ---- CSR build on capture stream ----
    cudaMemsetAsync(cur, 0, (size_t)n * sizeof(int), 0);
    hist_dst<<<(e / 4 + 255) / 256, 256>>>(dst, cur, e);
    int nb = (n + SCAN_BLK - 1) / SCAN_BLK;
    scan1<<<nb, SCAN_BLK>>>(cur, rp, bs, n);
    scan2<<<1, 128>>>(bs, nb);
    scan3<<<(n + 256) / 256, 256>>>(rp, cur, bs, n, e);
    build_edges<<<(e + 255) / 256, 256>>>(src, dst, ew, cur, edg, e);

    // ---- join ----
    cudaStreamWaitEvent(0, evG, 0);

    // ---- APPNP, scaled-fp16 pipeline ----
    // y_t = z_t / 16^t (exact power-of-two scaling)
    const float S = 16.0f;
    const int gblocks = (n * 32 + 255) / 256;

    // iter 0: y0 -> y1 (ya)
    gather_nodes<false><<<gblocks, 256>>>(
        edg, rp, y0, y0, z0, ya, 1.0f / S, ALPHA / S, n);

    // iters 1..8: y_t -> y_{t+1}   (t=8 output lands in bufs[0]=ya)
    __half* bufs[2] = { ya, yb };
    float pw = S * S;
    for (int t = 1; t <= 8; t++) {
        __half* zin  = bufs[(t + 1) & 1];
        __half* zout = bufs[t & 1];
        gather_nodes<false><<<gblocks, 256>>>(
            edg, rp, zin, y0, z0, zout, 1.0f / S, ALPHA / pw, n);
        pw *= S;
    }

    // iter 9 (final): input y9 = bufs[0], fp32 z0 injection, fused log_softmax
    float S9 = 1.0f;
    for (int k = 0; k < 9; k++) S9 *= S;
    gather_nodes<true><<<gblocks, 256>>>(
        edg, rp, bufs[0], y0, z0, out, S9, ALPHA, n);
}

// round 13
// speedup vs baseline: 1.2804x; 1.1384x over previous
#include <cuda_runtime.h>
#include <cuda_fp16.h>
#include <cuda_bf16.h>
#include <cstdint>

// ---------------- problem constants ----------------
#define MAXN    100000
#define MAXE    3200000
#define NFEAT   512
#define HID     64
#define NCLASS  64
#define ALPHA   0.1f
#define NITER   10
#define SCAN_BLK 1024

// ---------------- static device scratch ----------------
__device__ float    g_z0[MAXN * NCLASS];   // fp32 base prediction
__device__ __half   g_y0[MAXN * NCLASS];   // fp16 cast of z0
__device__ __half   g_ya[MAXN * NCLASS];   // fp16 scaled z ping
__device__ __half   g_yb[MAXN * NCLASS];   // fp16 scaled z pong
__device__ int      g_rowptr[MAXN + 1];
__device__ int      g_cursor[MAXN];
__device__ int      g_bsums[128];
__device__ uint32_t g_edges[MAXE];         // packed: src(17b) << 15 | w_q15(15b)

// ================= mma.sync helpers (baseline sm_80+, works on sm_103) ====
__device__ __forceinline__ uint32_t smem_u32(const void* p) {
    uint32_t a;
    asm("{ .reg .u64 t; cvta.to.shared.u64 t, %1; cvt.u32.u64 %0, t; }"
        : "=r"(a) : "l"(p));
    return a;
}
__device__ __forceinline__ void ldsm_x4(uint32_t* r, uint32_t addr) {
    asm volatile("ldmatrix.sync.aligned.m8n8.x4.shared.b16 {%0,%1,%2,%3}, [%4];"
                 : "=r"(r[0]), "=r"(r[1]), "=r"(r[2]), "=r"(r[3]) : "r"(addr));
}
__device__ __forceinline__ void ldsm_x4_t(uint32_t* r, uint32_t addr) {
    asm volatile("ldmatrix.sync.aligned.m8n8.x4.trans.shared.b16 {%0,%1,%2,%3}, [%4];"
                 : "=r"(r[0]), "=r"(r[1]), "=r"(r[2]), "=r"(r[3]) : "r"(addr));
}
__device__ __forceinline__ void mma_bf16(
    float* d, const uint32_t* a, const uint32_t* b)
{
    asm volatile(
        "mma.sync.aligned.m16n8k16.row.col.f32.bf16.bf16.f32 "
        "{%0,%1,%2,%3}, {%4,%5,%6,%7}, {%8,%9}, {%0,%1,%2,%3};"
        : "+f"(d[0]), "+f"(d[1]), "+f"(d[2]), "+f"(d[3])
        : "r"(a[0]), "r"(a[1]), "r"(a[2]), "r"(a[3]), "r"(b[0]), "r"(b[1]));
}
__device__ __forceinline__ uint32_t pkbf2(float a, float b) {
    __nv_bfloat162 h = __floats2bfloat162_rn(a, b);
    return *reinterpret_cast<uint32_t*>(&h);
}

// =================================================================
// mma.sync fused GEMM: z0 = relu(x @ W1) @ W2, bf16 hi/lo 3-term split.
// Epilogue also emits y0 = fp16(z0) (fused cvt).
// =================================================================
#define GM_AHI 0
#define GM_ALO 36864
#define GM_BHI 73728
#define GM_BLO 82944
#define GM_SMEM 92160

__global__ __launch_bounds__(256) void gemm_mma(
    const float* __restrict__ X, const float* __restrict__ W1,
    const float* __restrict__ W2, float* __restrict__ Z0,
    __half* __restrict__ Y0, int n)
{
    extern __shared__ char smc[];
    const uint32_t sb = smem_u32(smc);
    const int tid = threadIdx.x;
    const int wid = tid >> 5;
    const int l   = tid & 31;
    const int bm  = blockIdx.x * 256;
    const int wr  = wid * 32;

    const int arow = (l & 7) + ((l >> 3) & 1) * 8;
    const uint32_t akb = ((l >> 4) & 1) * 16;
    const uint32_t aoff0 = (uint32_t)(wr + arow) * 144 + akb;
    const uint32_t aoff1 = (uint32_t)(wr + 16 + arow) * 144 + akb;
    const uint32_t boff  = (uint32_t)arow * 144 + akb;

    float acc[2][8][4];
#pragma unroll
    for (int am = 0; am < 2; am++)
#pragma unroll
        for (int na = 0; na < 8; na++)
#pragma unroll
            for (int q = 0; q < 4; q++) acc[am][na][q] = 0.f;

    for (int c = 0; c < 8; c++) {
#pragma unroll
        for (int it = 0; it < 16; it++) {
            int idx = it * 256 + tid;
            int r   = idx >> 4;
            int c4  = idx & 15;
            int row = bm + r;
            float4 v = make_float4(0.f, 0.f, 0.f, 0.f);
            if (row < n)
                v = *reinterpret_cast<const float4*>(X + (size_t)row * NFEAT + c * 64 + c4 * 4);
            uint32_t h0 = pkbf2(v.x, v.y), h1 = pkbf2(v.z, v.w);
            __nv_bfloat162 bh0 = *reinterpret_cast<__nv_bfloat162*>(&h0);
            __nv_bfloat162 bh1 = *reinterpret_cast<__nv_bfloat162*>(&h1);
            float2 f0 = __bfloat1622float2(bh0);
            float2 f1 = __bfloat1622float2(bh1);
            uint32_t l0 = pkbf2(v.x - f0.x, v.y - f0.y);
            uint32_t l1 = pkbf2(v.z - f1.x, v.w - f1.y);
            uint32_t off = (uint32_t)r * 144 + c4 * 8;
            *reinterpret_cast<uint2*>(smc + GM_AHI + off) = make_uint2(h0, h1);
            *reinterpret_cast<uint2*>(smc + GM_ALO + off) = make_uint2(l0, l1);
        }
#pragma unroll
        for (int it = 0; it < 4; it++) {
            int idx = it * 256 + tid;
            int k   = idx >> 4;
            int c4  = idx & 15;
            float4 v = *reinterpret_cast<const float4*>(W1 + (size_t)(c * 64 + k) * HID + c4 * 4);
            uint32_t h0 = pkbf2(v.x, v.y), h1 = pkbf2(v.z, v.w);
            __nv_bfloat162 bh0 = *reinterpret_cast<__nv_bfloat162*>(&h0);
            __nv_bfloat162 bh1 = *reinterpret_cast<__nv_bfloat162*>(&h1);
            float2 f0 = __bfloat1622float2(bh0);
            float2 f1 = __bfloat1622float2(bh1);
            uint32_t l0 = pkbf2(v.x - f0.x, v.y - f0.y);
            uint32_t l1 = pkbf2(v.z - f1.x, v.w - f1.y);
            uint32_t off = (uint32_t)k * 144 + c4 * 8;
            *reinterpret_cast<uint2*>(smc + GM_BHI + off) = make_uint2(h0, h1);
            *reinterpret_cast<uint2*>(smc + GM_BLO + off) = make_uint2(l0, l1);
        }
        __syncthreads();

#pragma unroll
        for (int s = 0; s < 4; s++) {
            uint32_t ah0[4], ah1[4], al0[4], al1[4];
            ldsm_x4(ah0, sb + GM_AHI + aoff0 + s * 32);
            ldsm_x4(ah1, sb + GM_AHI + aoff1 + s * 32);
            ldsm_x4(al0, sb + GM_ALO + aoff0 + s * 32);
            ldsm_x4(al1, sb + GM_ALO + aoff1 + s * 32);
            uint32_t bh[8][2], bl[8][2];
#pragma unroll
            for (int p = 0; p < 4; p++) {
                uint32_t r4[4];
                ldsm_x4_t(r4, sb + GM_BHI + s * 2304 + p * 32 + boff);
                bh[2 * p][0] = r4[0]; bh[2 * p][1] = r4[1];
                bh[2 * p + 1][0] = r4[2]; bh[2 * p + 1][1] = r4[3];
                ldsm_x4_t(r4, sb + GM_BLO + s * 2304 + p * 32 + boff);
                bl[2 * p][0] = r4[0]; bl[2 * p][1] = r4[1];
                bl[2 * p + 1][0] = r4[2]; bl[2 * p + 1][1] = r4[3];
            }
#pragma unroll
            for (int na = 0; na < 8; na++) {
                mma_bf16(acc[0][na], ah0, bh[na]);
                mma_bf16(acc[1][na], ah1, bh[na]);
                mma_bf16(acc[0][na], al0, bh[na]);
                mma_bf16(acc[1][na], al1, bh[na]);
                mma_bf16(acc[0][na], ah0, bl[na]);
                mma_bf16(acc[1][na], ah1, bl[na]);
            }
        }
        __syncthreads();
    }

    // ---- phase 2 ----
    uint32_t a2h[2][4][4], a2l[2][4][4];
#pragma unroll
    for (int am = 0; am < 2; am++)
#pragma unroll
        for (int s = 0; s < 4; s++) {
            float v00 = fmaxf(acc[am][2 * s][0], 0.f);
            float v01 = fmaxf(acc[am][2 * s][1], 0.f);
            float v02 = fmaxf(acc[am][2 * s][2], 0.f);
            float v03 = fmaxf(acc[am][2 * s][3], 0.f);
            float v10 = fmaxf(acc[am][2 * s + 1][0], 0.f);
            float v11 = fmaxf(acc[am][2 * s + 1][1], 0.f);
            float v12 = fmaxf(acc[am][2 * s + 1][2], 0.f);
            float v13 = fmaxf(acc[am][2 * s + 1][3], 0.f);
            uint32_t h;
            h = pkbf2(v00, v01); a2h[am][s][0] = h;
            { __nv_bfloat162 b = *reinterpret_cast<__nv_bfloat162*>(&h); float2 f = __bfloat1622float2(b);
              a2l[am][s][0] = pkbf2(v00 - f.x, v01 - f.y); }
            h = pkbf2(v02, v03); a2h[am][s][1] = h;
            { __nv_bfloat162 b = *reinterpret_cast<__nv_bfloat162*>(&h); float2 f = __bfloat1622float2(b);
              a2l[am][s][1] = pkbf2(v02 - f.x, v03 - f.y); }
            h = pkbf2(v10, v11); a2h[am][s][2] = h;
            { __nv_bfloat162 b = *reinterpret_cast<__nv_bfloat162*>(&h); float2 f = __bfloat1622float2(b);
              a2l[am][s][2] = pkbf2(v10 - f.x, v11 - f.y); }
            h = pkbf2(v12, v13); a2h[am][s][3] = h;
            { __nv_bfloat162 b = *reinterpret_cast<__nv_bfloat162*>(&h); float2 f = __bfloat1622float2(b);
              a2l[am][s][3] = pkbf2(v12 - f.x, v13 - f.y); }
        }

#pragma unroll
    for (int am = 0; am < 2; am++)
#pragma unroll
        for (int na = 0; na < 8; na++)
#pragma unroll
            for (int q = 0; q < 4; q++) acc[am][na][q] = 0.f;

#pragma unroll
    for (int it = 0; it < 4; it++) {
        int idx = it * 256 + tid;
        int k   = idx >> 4;
        int c4  = idx & 15;
        float4 v = *reinterpret_cast<const float4*>(W2 + (size_t)k * NCLASS + c4 * 4);
        uint32_t h0 = pkbf2(v.x, v.y), h1 = pkbf2(v.z, v.w);
        __nv_bfloat162 bh0 = *reinterpret_cast<__nv_bfloat162*>(&h0);
        __nv_bfloat162 bh1 = *reinterpret_cast<__nv_bfloat162*>(&h1);
        float2 f0 = __bfloat1622float2(bh0);
        float2 f1 = __bfloat1622float2(bh1);
        uint32_t l0 = pkbf2(v.x - f0.x, v.y - f0.y);
        uint32_t l1 = pkbf2(v.z - f1.x, v.w - f1.y);
        uint32_t off = (uint32_t)k * 144 + c4 * 8;
        *reinterpret_cast<uint2*>(smc + GM_BHI + off) = make_uint2(h0, h1);
        *reinterpret_cast<uint2*>(smc + GM_BLO + off) = make_uint2(l0, l1);
    }
    __syncthreads();

#pragma unroll
    for (int s = 0; s < 4; s++) {
        uint32_t bh[8][2], bl[8][2];
#pragma unroll
        for (int p = 0; p < 4; p++) {
            uint32_t r4[4];
            ldsm_x4_t(r4, sb + GM_BHI + s * 2304 + p * 32 + boff);
            bh[2 * p][0] = r4[0]; bh[2 * p][1] = r4[1];
            bh[2 * p + 1][0] = r4[2]; bh[2 * p + 1][1] = r4[3];
            ldsm_x4_t(r4, sb + GM_BLO + s * 2304 + p * 32 + boff);
            bl[2 * p][0] = r4[0]; bl[2 * p][1] = r4[1];
            bl[2 * p + 1][0] = r4[2]; bl[2 * p + 1][1] = r4[3];
        }
#pragma unroll
        for (int na = 0; na < 8; na++) {
            mma_bf16(acc[0][na], a2h[0][s], bh[na]);
            mma_bf16(acc[1][na], a2h[1][s], bh[na]);
            mma_bf16(acc[0][na], a2l[0][s], bh[na]);
            mma_bf16(acc[1][na], a2l[1][s], bh[na]);
            mma_bf16(acc[0][na], a2h[0][s], bl[na]);
            mma_bf16(acc[1][na], a2h[1][s], bl[na]);
        }
    }

    // store z0 (fp32) + y0 (fp16, fused cast)
#pragma unroll
    for (int am = 0; am < 2; am++) {
        int r0 = bm + wr + am * 16 + (l >> 2);
        int col = (l & 3) * 2;
#pragma unroll
        for (int na = 0; na < 8; na++) {
            if (r0 < n) {
                *reinterpret_cast<float2*>(Z0 + (size_t)r0 * NCLASS + na * 8 + col) =
                    make_float2(acc[am][na][0], acc[am][na][1]);
                __half2 hh = __floats2half2_rn(acc[am][na][0], acc[am][na][1]);
                *reinterpret_cast<__half2*>(Y0 + (size_t)r0 * NCLASS + na * 8 + col) = hh;
            }
            if (r0 + 8 < n) {
                *reinterpret_cast<float2*>(Z0 + (size_t)(r0 + 8) * NCLASS + na * 8 + col) =
                    make_float2(acc[am][na][2], acc[am][na][3]);
                __half2 hh = __floats2half2_rn(acc[am][na][2], acc[am][na][3]);
                *reinterpret_cast<__half2*>(Y0 + (size_t)(r0 + 8) * NCLASS + na * 8 + col) = hh;
            }
        }
    }
}

// =================================================================
// CSR construction (3-kernel scan — proven ~12us)
// =================================================================
__global__ __launch_bounds__(256) void hist_dst(
    const int* __restrict__ dst, int* __restrict__ cnt, int e)
{
    int i = blockIdx.x * 256 + threadIdx.x;
    if (i < e) atomicAdd(&cnt[dst[i]], 1);
}

__global__ __launch_bounds__(SCAN_BLK) void scan1(
    const int* __restrict__ cnt, int* __restrict__ rowptr,
    int* __restrict__ bsums, int n)
{
    __shared__ int sh[SCAN_BLK];
    int t = threadIdx.x;
    int i = blockIdx.x * SCAN_BLK + t;
    int v = (i < n) ? cnt[i] : 0;
    sh[t] = v;
    __syncthreads();
#pragma unroll
    for (int off = 1; off < SCAN_BLK; off <<= 1) {
        int x = (t >= off) ? sh[t - off] : 0;
        __syncthreads();
        sh[t] += x;
        __syncthreads();
    }
    int incl = sh[t];
    if (i < n) rowptr[i] = incl - v;
    if (t == SCAN_BLK - 1) bsums[blockIdx.x] = incl;
}

__global__ __launch_bounds__(128) void scan2(int* __restrict__ bsums, int nb)
{
    __shared__ int sh[128];
    int t = threadIdx.x;
    int v = (t < nb) ? bsums[t] : 0;
    sh[t] = v;
    __syncthreads();
#pragma unroll
    for (int off = 1; off < 128; off <<= 1) {
        int x = (t >= off) ? sh[t - off] : 0;
        __syncthreads();
        sh[t] += x;
        __syncthreads();
    }
    if (t < nb) bsums[t] = sh[t] - v;
}

__global__ __launch_bounds__(256) void scan3(
    int* __restrict__ rowptr, int* __restrict__ cursor,
    const int* __restrict__ bsums, int n, int e)
{
    int i = blockIdx.x * 256 + threadIdx.x;
    if (i < n) {
        int v = rowptr[i] + bsums[i >> 10];
        rowptr[i] = v;
        cursor[i] = v;
    }
    if (i == n) rowptr[n] = e;
}

// pack: src (17 bits, <<15) | weight q15 (15 bits)
__global__ __launch_bounds__(256) void build_edges(
    const int* __restrict__ src, const int* __restrict__ dst,
    const float* __restrict__ ew, int* __restrict__ cursor,
    uint32_t* __restrict__ edges, int e)
{
    int i = blockIdx.x * 256 + threadIdx.x;
    if (i < e) {
        int d = dst[i];
        int pos = atomicAdd(&cursor[d], 1);
        int q = __float2int_rn(ew[i] * 32768.0f);
        if (q > 32767) q = 32767;
        if (q < 0) q = 0;
        edges[pos] = ((uint32_t)src[i] << 15) | (uint32_t)q;
    }
}

// =================================================================
// gather: TWO nodes per warp (16 lanes each), 2 sub-groups of 8
// per node, 2-deep unroll (8 rows in flight/warp). Packed 4B edges.
// =================================================================
__device__ __forceinline__ void load_row8_h(
    const __half* zin, uint32_t node, int c8, float* v)
{
    float4 raw = __ldg(reinterpret_cast<const float4*>(zin + (size_t)node * NCLASS) + c8);
    const __half2* h = reinterpret_cast<const __half2*>(&raw);
#pragma unroll
    for (int j = 0; j < 4; j++) {
        float2 f = __half22float2(h[j]);
        v[2 * j]     = f.x;
        v[2 * j + 1] = f.y;
    }
}
__device__ __forceinline__ void load_row8_f(
    const float* zin, int node, int c8, float* v)
{
    const float4* p = reinterpret_cast<const float4*>(zin + (size_t)node * NCLASS);
    float4 a = __ldg(p + 2 * c8);
    float4 b = __ldg(p + 2 * c8 + 1);
    v[0] = a.x; v[1] = a.y; v[2] = a.z; v[3] = a.w;
    v[4] = b.x; v[5] = b.y; v[6] = b.z; v[7] = b.w;
}

#define WQ 3.0517578125e-5f   // 1/32768

template<bool LAST>
__global__ __launch_bounds__(256) void gather_nodes(
    const uint32_t* __restrict__ edges, const int* __restrict__ rowptr,
    const __half* __restrict__ zin, const __half* __restrict__ y0,
    const float* __restrict__ z0, void* __restrict__ zout_v,
    float c1, float c0, int n)
{
    int lane  = threadIdx.x & 31;
    int wpair = (blockIdx.x * 256 + threadIdx.x) >> 5;   // warp index
    int node  = wpair * 2 + (lane >> 4);                 // 2 nodes per warp
    int sub2  = (lane >> 3) & 1;                         // sub-group within node
    int c8    = lane & 7;

    bool valid = (node < n);
    int beg = 0, end = 0;
    if (valid) {
        beg = __ldg(&rowptr[node]);
        end = __ldg(&rowptr[node + 1]);
    }

    float acc[8];
#pragma unroll
    for (int j = 0; j < 8; j++) acc[j] = 0.f;

    int i = beg + sub2;
    // 2 edges per sub-group in flight (8 rows per warp across 2 nodes)
    for (; i + 2 < end; i += 4) {
        uint32_t e0 = __ldg(&edges[i]);
        uint32_t e1 = __ldg(&edges[i + 2]);
        float v0[8], v1[8];
        load_row8_h(zin, e0 >> 15, c8, v0);
        load_row8_h(zin, e1 >> 15, c8, v1);
        float w0 = (float)(e0 & 0x7FFFu) * WQ;
        float w1 = (float)(e1 & 0x7FFFu) * WQ;
#pragma unroll
        for (int j = 0; j < 8; j++) acc[j] = fmaf(w0, v0[j], acc[j]);
#pragma unroll
        for (int j = 0; j < 8; j++) acc[j] = fmaf(w1, v1[j], acc[j]);
    }
    for (; i < end; i += 2) {
        uint32_t e0 = __ldg(&edges[i]);
        float v0[8];
        load_row8_h(zin, e0 >> 15, c8, v0);
        float w0 = (float)(e0 & 0x7FFFu) * WQ;
#pragma unroll
        for (int j = 0; j < 8; j++) acc[j] = fmaf(w0, v0[j], acc[j]);
    }

    // combine the two sub-groups of this node (xor 8 stays inside 16-lane half)
    const unsigned FULL = 0xFFFFFFFFu;
#pragma unroll
    for (int j = 0; j < 8; j++)
        acc[j] += __shfl_xor_sync(FULL, acc[j], 8);

    float z0v[8];
    int nodec = valid ? node : 0;
    if (LAST) load_row8_f(z0, nodec, c8, z0v);
    else      load_row8_h(y0, (uint32_t)nodec, c8, z0v);
    float o[8];
#pragma unroll
    for (int j = 0; j < 8; j++) o[j] = fmaf(c0, z0v[j], c1 * acc[j]);

    if (!LAST) {
        if (sub2 == 0 && valid) {
            __half2 h[4];
#pragma unroll
            for (int j = 0; j < 4; j++)
                h[j] = __floats2half2_rn(o[2 * j], o[2 * j + 1]);
            __half* zo = (__half*)zout_v;
            *(reinterpret_cast<float4*>(zo + (size_t)node * NCLASS) + c8) =
                *reinterpret_cast<float4*>(h);
        }
    } else {
        // log_softmax: stats over the 8 c8-lanes (xor 1,2,4 stay inside group)
        float m = o[0];
#pragma unroll
        for (int j = 1; j < 8; j++) m = fmaxf(m, o[j]);
#pragma unroll
        for (int off = 1; off < 8; off <<= 1)
            m = fmaxf(m, __shfl_xor_sync(FULL, m, off));
        float s = 0.f;
#pragma unroll
        for (int j = 0; j < 8; j++) s += __expf(o[j] - m);
#pragma unroll
        for (int off = 1; off < 8; off <<= 1)
            s += __shfl_xor_sync(FULL, s, off);
        float l = m + __logf(s);
        if (sub2 == 0 && valid) {
            float* zo = (float*)zout_v;
            float4 r0 = make_float4(o[0] - l, o[1] - l, o[2] - l, o[3] - l);
            float4 r1 = make_float4(o[4] - l, o[5] - l, o[6] - l, o[7] - l);
            float4* p = reinterpret_cast<float4*>(zo + (size_t)node * NCLASS);
            p[2 * c8]     = r0;
            p[2 * c8 + 1] = r1;
        }
    }
}

// =================================================================
// launch
// =================================================================
extern "C" void kernel_launch(void* const* d_in, const int* in_sizes, int n_in,
                              void* d_out, int out_size)
{
    const float* x   = (const float*)d_in[0];
    const int*   ei  = (const int*)  d_in[1];
    const float* ew  = (const float*)d_in[2];
    const float* W1  = (const float*)d_in[3];
    const float* W2  = (const float*)d_in[4];
    float*       out = (float*)d_out;

    const int n = in_sizes[0] / NFEAT;
    const int e = in_sizes[2];
    const int* src = ei;
    const int* dst = ei + e;

    float*    z0  = nullptr; cudaGetSymbolAddress((void**)&z0,  g_z0);
    __half*   y0  = nullptr; cudaGetSymbolAddress((void**)&y0,  g_y0);
    __half*   ya  = nullptr; cudaGetSymbolAddress((void**)&ya,  g_ya);
    __half*   yb  = nullptr; cudaGetSymbolAddress((void**)&yb,  g_yb);
    int*      rp  = nullptr; cudaGetSymbolAddress((void**)&rp,  g_rowptr);
    int*      cur = nullptr; cudaGetSymbolAddress((void**)&cur, g_cursor);
    int*      bs  = nullptr; cudaGetSymbolAddress((void**)&bs,  g_bsums);
    uint32_t* edg = nullptr; cudaGetSymbolAddress((void**)&edg, g_edges);

    static cudaStream_t sG = nullptr;
    static cudaEvent_t  evF = nullptr, evG = nullptr;
    if (sG == nullptr) {
        cudaStreamCreateWithFlags(&sG, cudaStreamNonBlocking);
        cudaEventCreateWithFlags(&evF, cudaEventDisableTiming);
        cudaEventCreateWithFlags(&evG, cudaEventDisableTiming);
        cudaFuncSetAttribute(gemm_mma,
            cudaFuncAttributeMaxDynamicSharedMemorySize, GM_SMEM);
    }

    // ---- fork: tensor-core GEMM (with fused fp16 cast) on side stream ----
    cudaEventRecord(evF, 0);
    cudaStreamWaitEvent(sG, evF, 0);
    gemm_mma<<<(n + 255) / 256, 256, GM_SMEM, sG>>>(x, W1, W2, z0, y0, n);
    cudaEventRecord(evG, sG);

    // ---- CSR build on capture stream ----
    cudaMemsetAsync(cur, 0, (size_t)n * sizeof(int), 0);
    hist_dst<<<(e + 255) / 256, 256>>>(dst, cur, e);
    int nb = (n + SCAN_BLK - 1) / SCAN_BLK;
    scan1<<<nb, SCAN_BLK>>>(cur, rp, bs, n);
    scan2<<<1, 128>>>(bs, nb);
    scan3<<<(n + 256) / 256, 256>>>(rp, cur, bs, n, e);
    build_edges<<<(e + 255) / 256, 256>>>(src, dst, ew, cur, edg, e);

    // ---- join ----
    cudaStreamWaitEvent(0, evG, 0);

    // ---- APPNP, scaled-fp16 pipeline ----
    // y_t = z_t / 16^t (exact power-of-two scaling)
    const float S = 16.0f;
    const int gblocks = (n * 16 + 255) / 256;   // 2 nodes per warp

    // iter 0: y0 -> y1 (ya)
    gather_nodes<false><<<gblocks, 256>>>(
        edg, rp, y0, y0, z0, ya, 1.0f / S, ALPHA / S, n);

    // iters 1..8: y_t -> y_{t+1}   (t=8 output lands in bufs[0]=ya)
    __half* bufs[2] = { ya, yb };
    float pw = S * S;
    for (int t = 1; t <= 8; t++) {
        __half* zin  = bufs[(t + 1) & 1];
        __half* zout = bufs[t & 1];
        gather_nodes<false><<<gblocks, 256>>>(
            edg, rp, zin, y0, z0, zout, 1.0f / S, ALPHA / pw, n);
        pw *= S;
    }

    // iter 9 (final): input y9 = bufs[0], fp32 z0 injection, fused log_softmax
    float S9 = 1.0f;
    for (int k = 0; k < 9; k++) S9 *= S;
    gather_nodes<true><<<gblocks, 256>>>(
        edg, rp, bufs[0], y0, z0, out, S9, ALPHA, n);
}

// round 14
// speedup vs baseline: 1.3239x; 1.0339x over previous
#include <cuda_runtime.h>
#include <cuda_fp16.h>
#include <cuda_bf16.h>
#include <cstdint>

// ---------------- problem constants ----------------
#define MAXN    100000
#define MAXE    3200000
#define NFEAT   512
#define HID     64
#define NCLASS  64
#define ALPHA   0.1f
#define NITER   10
#define SCAN_BLK 1024

// ---------------- static device scratch ----------------
__device__ float    g_z0[MAXN * NCLASS];   // fp32 base prediction
__device__ __half   g_y0[MAXN * NCLASS];   // fp16 cast of z0
__device__ __half   g_ya[MAXN * NCLASS];   // fp16 scaled z ping
__device__ __half   g_yb[MAXN * NCLASS];   // fp16 scaled z pong
__device__ int      g_rowptr[MAXN + 1];
__device__ int      g_cursor[MAXN];
__device__ int      g_bsums[128];
__device__ uint32_t g_edges[MAXE];         // packed: src(17b) << 15 | w_q15(15b)

// ================= mma.sync helpers (baseline sm_80+, works on sm_103) ====
__device__ __forceinline__ uint32_t smem_u32(const void* p) {
    uint32_t a;
    asm("{ .reg .u64 t; cvta.to.shared.u64 t, %1; cvt.u32.u64 %0, t; }"
        : "=r"(a) : "l"(p));
    return a;
}
__device__ __forceinline__ void ldsm_x4(uint32_t* r, uint32_t addr) {
    asm volatile("ldmatrix.sync.aligned.m8n8.x4.shared.b16 {%0,%1,%2,%3}, [%4];"
                 : "=r"(r[0]), "=r"(r[1]), "=r"(r[2]), "=r"(r[3]) : "r"(addr));
}
__device__ __forceinline__ void ldsm_x4_t(uint32_t* r, uint32_t addr) {
    asm volatile("ldmatrix.sync.aligned.m8n8.x4.trans.shared.b16 {%0,%1,%2,%3}, [%4];"
                 : "=r"(r[0]), "=r"(r[1]), "=r"(r[2]), "=r"(r[3]) : "r"(addr));
}
__device__ __forceinline__ void mma_bf16(
    float* d, const uint32_t* a, const uint32_t* b)
{
    asm volatile(
        "mma.sync.aligned.m16n8k16.row.col.f32.bf16.bf16.f32 "
        "{%0,%1,%2,%3}, {%4,%5,%6,%7}, {%8,%9}, {%0,%1,%2,%3};"
        : "+f"(d[0]), "+f"(d[1]), "+f"(d[2]), "+f"(d[3])
        : "r"(a[0]), "r"(a[1]), "r"(a[2]), "r"(a[3]), "r"(b[0]), "r"(b[1]));
}
__device__ __forceinline__ uint32_t pkbf2(float a, float b) {
    __nv_bfloat162 h = __floats2bfloat162_rn(a, b);
    return *reinterpret_cast<uint32_t*>(&h);
}

// =================================================================
// mma.sync fused GEMM: z0 = relu(x @ W1) @ W2, bf16 hi/lo 3-term split.
// Epilogue also emits y0 = fp16(z0) (fused cvt).
// =================================================================
#define GM_AHI 0
#define GM_ALO 36864
#define GM_BHI 73728
#define GM_BLO 82944
#define GM_SMEM 92160

__global__ __launch_bounds__(256) void gemm_mma(
    const float* __restrict__ X, const float* __restrict__ W1,
    const float* __restrict__ W2, float* __restrict__ Z0,
    __half* __restrict__ Y0, int n)
{
    extern __shared__ char smc[];
    const uint32_t sb = smem_u32(smc);
    const int tid = threadIdx.x;
    const int wid = tid >> 5;
    const int l   = tid & 31;
    const int bm  = blockIdx.x * 256;
    const int wr  = wid * 32;

    const int arow = (l & 7) + ((l >> 3) & 1) * 8;
    const uint32_t akb = ((l >> 4) & 1) * 16;
    const uint32_t aoff0 = (uint32_t)(wr + arow) * 144 + akb;
    const uint32_t aoff1 = (uint32_t)(wr + 16 + arow) * 144 + akb;
    const uint32_t boff  = (uint32_t)arow * 144 + akb;

    float acc[2][8][4];
#pragma unroll
    for (int am = 0; am < 2; am++)
#pragma unroll
        for (int na = 0; na < 8; na++)
#pragma unroll
            for (int q = 0; q < 4; q++) acc[am][na][q] = 0.f;

    for (int c = 0; c < 8; c++) {
#pragma unroll
        for (int it = 0; it < 16; it++) {
            int idx = it * 256 + tid;
            int r   = idx >> 4;
            int c4  = idx & 15;
            int row = bm + r;
            float4 v = make_float4(0.f, 0.f, 0.f, 0.f);
            if (row < n)
                v = *reinterpret_cast<const float4*>(X + (size_t)row * NFEAT + c * 64 + c4 * 4);
            uint32_t h0 = pkbf2(v.x, v.y), h1 = pkbf2(v.z, v.w);
            __nv_bfloat162 bh0 = *reinterpret_cast<__nv_bfloat162*>(&h0);
            __nv_bfloat162 bh1 = *reinterpret_cast<__nv_bfloat162*>(&h1);
            float2 f0 = __bfloat1622float2(bh0);
            float2 f1 = __bfloat1622float2(bh1);
            uint32_t l0 = pkbf2(v.x - f0.x, v.y - f0.y);
            uint32_t l1 = pkbf2(v.z - f1.x, v.w - f1.y);
            uint32_t off = (uint32_t)r * 144 + c4 * 8;
            *reinterpret_cast<uint2*>(smc + GM_AHI + off) = make_uint2(h0, h1);
            *reinterpret_cast<uint2*>(smc + GM_ALO + off) = make_uint2(l0, l1);
        }
#pragma unroll
        for (int it = 0; it < 4; it++) {
            int idx = it * 256 + tid;
            int k   = idx >> 4;
            int c4  = idx & 15;
            float4 v = *reinterpret_cast<const float4*>(W1 + (size_t)(c * 64 + k) * HID + c4 * 4);
            uint32_t h0 = pkbf2(v.x, v.y), h1 = pkbf2(v.z, v.w);
            __nv_bfloat162 bh0 = *reinterpret_cast<__nv_bfloat162*>(&h0);
            __nv_bfloat162 bh1 = *reinterpret_cast<__nv_bfloat162*>(&h1);
            float2 f0 = __bfloat1622float2(bh0);
            float2 f1 = __bfloat1622float2(bh1);
            uint32_t l0 = pkbf2(v.x - f0.x, v.y - f0.y);
            uint32_t l1 = pkbf2(v.z - f1.x, v.w - f1.y);
            uint32_t off = (uint32_t)k * 144 + c4 * 8;
            *reinterpret_cast<uint2*>(smc + GM_BHI + off) = make_uint2(h0, h1);
            *reinterpret_cast<uint2*>(smc + GM_BLO + off) = make_uint2(l0, l1);
        }
        __syncthreads();

#pragma unroll
        for (int s = 0; s < 4; s++) {
            uint32_t ah0[4], ah1[4], al0[4], al1[4];
            ldsm_x4(ah0, sb + GM_AHI + aoff0 + s * 32);
            ldsm_x4(ah1, sb + GM_AHI + aoff1 + s * 32);
            ldsm_x4(al0, sb + GM_ALO + aoff0 + s * 32);
            ldsm_x4(al1, sb + GM_ALO + aoff1 + s * 32);
            uint32_t bh[8][2], bl[8][2];
#pragma unroll
            for (int p = 0; p < 4; p++) {
                uint32_t r4[4];
                ldsm_x4_t(r4, sb + GM_BHI + s * 2304 + p * 32 + boff);
                bh[2 * p][0] = r4[0]; bh[2 * p][1] = r4[1];
                bh[2 * p + 1][0] = r4[2]; bh[2 * p + 1][1] = r4[3];
                ldsm_x4_t(r4, sb + GM_BLO + s * 2304 + p * 32 + boff);
                bl[2 * p][0] = r4[0]; bl[2 * p][1] = r4[1];
                bl[2 * p + 1][0] = r4[2]; bl[2 * p + 1][1] = r4[3];
            }
#pragma unroll
            for (int na = 0; na < 8; na++) {
                mma_bf16(acc[0][na], ah0, bh[na]);
                mma_bf16(acc[1][na], ah1, bh[na]);
                mma_bf16(acc[0][na], al0, bh[na]);
                mma_bf16(acc[1][na], al1, bh[na]);
                mma_bf16(acc[0][na], ah0, bl[na]);
                mma_bf16(acc[1][na], ah1, bl[na]);
            }
        }
        __syncthreads();
    }

    // ---- phase 2 ----
    uint32_t a2h[2][4][4], a2l[2][4][4];
#pragma unroll
    for (int am = 0; am < 2; am++)
#pragma unroll
        for (int s = 0; s < 4; s++) {
            float v00 = fmaxf(acc[am][2 * s][0], 0.f);
            float v01 = fmaxf(acc[am][2 * s][1], 0.f);
            float v02 = fmaxf(acc[am][2 * s][2], 0.f);
            float v03 = fmaxf(acc[am][2 * s][3], 0.f);
            float v10 = fmaxf(acc[am][2 * s + 1][0], 0.f);
            float v11 = fmaxf(acc[am][2 * s + 1][1], 0.f);
            float v12 = fmaxf(acc[am][2 * s + 1][2], 0.f);
            float v13 = fmaxf(acc[am][2 * s + 1][3], 0.f);
            uint32_t h;
            h = pkbf2(v00, v01); a2h[am][s][0] = h;
            { __nv_bfloat162 b = *reinterpret_cast<__nv_bfloat162*>(&h); float2 f = __bfloat1622float2(b);
              a2l[am][s][0] = pkbf2(v00 - f.x, v01 - f.y); }
            h = pkbf2(v02, v03); a2h[am][s][1] = h;
            { __nv_bfloat162 b = *reinterpret_cast<__nv_bfloat162*>(&h); float2 f = __bfloat1622float2(b);
              a2l[am][s][1] = pkbf2(v02 - f.x, v03 - f.y); }
            h = pkbf2(v10, v11); a2h[am][s][2] = h;
            { __nv_bfloat162 b = *reinterpret_cast<__nv_bfloat162*>(&h); float2 f = __bfloat1622float2(b);
              a2l[am][s][2] = pkbf2(v10 - f.x, v11 - f.y); }
            h = pkbf2(v12, v13); a2h[am][s][3] = h;
            { __nv_bfloat162 b = *reinterpret_cast<__nv_bfloat162*>(&h); float2 f = __bfloat1622float2(b);
              a2l[am][s][3] = pkbf2(v12 - f.x, v13 - f.y); }
        }

#pragma unroll
    for (int am = 0; am < 2; am++)
#pragma unroll
        for (int na = 0; na < 8; na++)
#pragma unroll
            for (int q = 0; q < 4; q++) acc[am][na][q] = 0.f;

#pragma unroll
    for (int it = 0; it < 4; it++) {
        int idx = it * 256 + tid;
        int k   = idx >> 4;
        int c4  = idx & 15;
        float4 v = *reinterpret_cast<const float4*>(W2 + (size_t)k * NCLASS + c4 * 4);
        uint32_t h0 = pkbf2(v.x, v.y), h1 = pkbf2(v.z, v.w);
        __nv_bfloat162 bh0 = *reinterpret_cast<__nv_bfloat162*>(&h0);
        __nv_bfloat162 bh1 = *reinterpret_cast<__nv_bfloat162*>(&h1);
        float2 f0 = __bfloat1622float2(bh0);
        float2 f1 = __bfloat1622float2(bh1);
        uint32_t l0 = pkbf2(v.x - f0.x, v.y - f0.y);
        uint32_t l1 = pkbf2(v.z - f1.x, v.w - f1.y);
        uint32_t off = (uint32_t)k * 144 + c4 * 8;
        *reinterpret_cast<uint2*>(smc + GM_BHI + off) = make_uint2(h0, h1);
        *reinterpret_cast<uint2*>(smc + GM_BLO + off) = make_uint2(l0, l1);
    }
    __syncthreads();

#pragma unroll
    for (int s = 0; s < 4; s++) {
        uint32_t bh[8][2], bl[8][2];
#pragma unroll
        for (int p = 0; p < 4; p++) {
            uint32_t r4[4];
            ldsm_x4_t(r4, sb + GM_BHI + s * 2304 + p * 32 + boff);
            bh[2 * p][0] = r4[0]; bh[2 * p][1] = r4[1];
            bh[2 * p + 1][0] = r4[2]; bh[2 * p + 1][1] = r4[3];
            ldsm_x4_t(r4, sb + GM_BLO + s * 2304 + p * 32 + boff);
            bl[2 * p][0] = r4[0]; bl[2 * p][1] = r4[1];
            bl[2 * p + 1][0] = r4[2]; bl[2 * p + 1][1] = r4[3];
        }
#pragma unroll
        for (int na = 0; na < 8; na++) {
            mma_bf16(acc[0][na], a2h[0][s], bh[na]);
            mma_bf16(acc[1][na], a2h[1][s], bh[na]);
            mma_bf16(acc[0][na], a2l[0][s], bh[na]);
            mma_bf16(acc[1][na], a2l[1][s], bh[na]);
            mma_bf16(acc[0][na], a2h[0][s], bl[na]);
            mma_bf16(acc[1][na], a2h[1][s], bl[na]);
        }
    }

    // store z0 (fp32) + y0 (fp16, fused cast)
#pragma unroll
    for (int am = 0; am < 2; am++) {
        int r0 = bm + wr + am * 16 + (l >> 2);
        int col = (l & 3) * 2;
#pragma unroll
        for (int na = 0; na < 8; na++) {
            if (r0 < n) {
                *reinterpret_cast<float2*>(Z0 + (size_t)r0 * NCLASS + na * 8 + col) =
                    make_float2(acc[am][na][0], acc[am][na][1]);
                __half2 hh = __floats2half2_rn(acc[am][na][0], acc[am][na][1]);
                *reinterpret_cast<__half2*>(Y0 + (size_t)r0 * NCLASS + na * 8 + col) = hh;
            }
            if (r0 + 8 < n) {
                *reinterpret_cast<float2*>(Z0 + (size_t)(r0 + 8) * NCLASS + na * 8 + col) =
                    make_float2(acc[am][na][2], acc[am][na][3]);
                __half2 hh = __floats2half2_rn(acc[am][na][2], acc[am][na][3]);
                *reinterpret_cast<__half2*>(Y0 + (size_t)(r0 + 8) * NCLASS + na * 8 + col) = hh;
            }
        }
    }
}

// =================================================================
// CSR construction (3-kernel scan — proven ~12us)
// =================================================================
__global__ __launch_bounds__(256) void hist_dst(
    const int* __restrict__ dst, int* __restrict__ cnt, int e)
{
    int i = blockIdx.x * 256 + threadIdx.x;
    if (i < e) atomicAdd(&cnt[dst[i]], 1);
}

__global__ __launch_bounds__(SCAN_BLK) void scan1(
    const int* __restrict__ cnt, int* __restrict__ rowptr,
    int* __restrict__ bsums, int n)
{
    __shared__ int sh[SCAN_BLK];
    int t = threadIdx.x;
    int i = blockIdx.x * SCAN_BLK + t;
    int v = (i < n) ? cnt[i] : 0;
    sh[t] = v;
    __syncthreads();
#pragma unroll
    for (int off = 1; off < SCAN_BLK; off <<= 1) {
        int x = (t >= off) ? sh[t - off] : 0;
        __syncthreads();
        sh[t] += x;
        __syncthreads();
    }
    int incl = sh[t];
    if (i < n) rowptr[i] = incl - v;
    if (t == SCAN_BLK - 1) bsums[blockIdx.x] = incl;
}

__global__ __launch_bounds__(128) void scan2(int* __restrict__ bsums, int nb)
{
    __shared__ int sh[128];
    int t = threadIdx.x;
    int v = (t < nb) ? bsums[t] : 0;
    sh[t] = v;
    __syncthreads();
#pragma unroll
    for (int off = 1; off < 128; off <<= 1) {
        int x = (t >= off) ? sh[t - off] : 0;
        __syncthreads();
        sh[t] += x;
        __syncthreads();
    }
    if (t < nb) bsums[t] = sh[t] - v;
}

__global__ __launch_bounds__(256) void scan3(
    int* __restrict__ rowptr, int* __restrict__ cursor,
    const int* __restrict__ bsums, int n, int e)
{
    int i = blockIdx.x * 256 + threadIdx.x;
    if (i < n) {
        int v = rowptr[i] + bsums[i >> 10];
        rowptr[i] = v;
        cursor[i] = v;
    }
    if (i == n) rowptr[n] = e;
}

// pack: src (17 bits, <<15) | weight q15 (15 bits)
__global__ __launch_bounds__(256) void build_edges(
    const int* __restrict__ src, const int* __restrict__ dst,
    const float* __restrict__ ew, int* __restrict__ cursor,
    uint32_t* __restrict__ edges, int e)
{
    int i = blockIdx.x * 256 + threadIdx.x;
    if (i < e) {
        int d = dst[i];
        int pos = atomicAdd(&cursor[d], 1);
        int q = __float2int_rn(ew[i] * 32768.0f);
        if (q > 32767) q = 32767;
        if (q < 0) q = 0;
        edges[pos] = ((uint32_t)src[i] << 15) | (uint32_t)q;
    }
}

// =================================================================
// gather: FOUR nodes per warp (8 lanes each), sequential edges,
// 2-deep unroll (8 rows in flight/warp). No cross-group shuffles
// in the accumulation path. Packed 4B edges.
// =================================================================
__device__ __forceinline__ void load_row8_h(
    const __half* zin, uint32_t node, int c8, float* v)
{
    float4 raw = __ldg(reinterpret_cast<const float4*>(zin + (size_t)node * NCLASS) + c8);
    const __half2* h = reinterpret_cast<const __half2*>(&raw);
#pragma unroll
    for (int j = 0; j < 4; j++) {
        float2 f = __half22float2(h[j]);
        v[2 * j]     = f.x;
        v[2 * j + 1] = f.y;
    }
}
__device__ __forceinline__ void load_row8_f(
    const float* zin, int node, int c8, float* v)
{
    const float4* p = reinterpret_cast<const float4*>(zin + (size_t)node * NCLASS);
    float4 a = __ldg(p + 2 * c8);
    float4 b = __ldg(p + 2 * c8 + 1);
    v[0] = a.x; v[1] = a.y; v[2] = a.z; v[3] = a.w;
    v[4] = b.x; v[5] = b.y; v[6] = b.z; v[7] = b.w;
}

#define WQ 3.0517578125e-5f   // 1/32768

template<bool LAST>
__global__ __launch_bounds__(256) void gather_nodes(
    const uint32_t* __restrict__ edges, const int* __restrict__ rowptr,
    const __half* __restrict__ zin, const __half* __restrict__ y0,
    const float* __restrict__ z0, void* __restrict__ zout_v,
    float c1, float c0, int n)
{
    int lane = threadIdx.x & 31;
    int warp = (blockIdx.x * 256 + threadIdx.x) >> 5;
    int node = warp * 4 + (lane >> 3);   // 4 nodes per warp
    int c8   = lane & 7;

    bool valid = (node < n);
    int beg = 0, end = 0;
    if (valid) {
        beg = __ldg(&rowptr[node]);
        end = __ldg(&rowptr[node + 1]);
    }

    float acc[8];
#pragma unroll
    for (int j = 0; j < 8; j++) acc[j] = 0.f;

    int i = beg;
    // 2 edges in flight per node (8 rows per warp across 4 nodes)
    for (; i + 1 < end; i += 2) {
        uint32_t e0 = __ldg(&edges[i]);
        uint32_t e1 = __ldg(&edges[i + 1]);
        float v0[8], v1[8];
        load_row8_h(zin, e0 >> 15, c8, v0);
        load_row8_h(zin, e1 >> 15, c8, v1);
        float w0 = (float)(e0 & 0x7FFFu) * WQ;
        float w1 = (float)(e1 & 0x7FFFu) * WQ;
#pragma unroll
        for (int j = 0; j < 8; j++) acc[j] = fmaf(w0, v0[j], acc[j]);
#pragma unroll
        for (int j = 0; j < 8; j++) acc[j] = fmaf(w1, v1[j], acc[j]);
    }
    if (i < end) {
        uint32_t e0 = __ldg(&edges[i]);
        float v0[8];
        load_row8_h(zin, e0 >> 15, c8, v0);
        float w0 = (float)(e0 & 0x7FFFu) * WQ;
#pragma unroll
        for (int j = 0; j < 8; j++) acc[j] = fmaf(w0, v0[j], acc[j]);
    }

    // no cross-group reduction needed: each 8-lane group owns the full row
    float z0v[8];
    int nodec = valid ? node : 0;
    if (LAST) load_row8_f(z0, nodec, c8, z0v);
    else      load_row8_h(y0, (uint32_t)nodec, c8, z0v);
    float o[8];
#pragma unroll
    for (int j = 0; j < 8; j++) o[j] = fmaf(c0, z0v[j], c1 * acc[j]);

    if (!LAST) {
        if (valid) {
            __half2 h[4];
#pragma unroll
            for (int j = 0; j < 4; j++)
                h[j] = __floats2half2_rn(o[2 * j], o[2 * j + 1]);
            __half* zo = (__half*)zout_v;
            *(reinterpret_cast<float4*>(zo + (size_t)node * NCLASS) + c8) =
                *reinterpret_cast<float4*>(h);
        }
    } else {
        // log_softmax: stats over the 8 c8-lanes (xor 1,2,4 stay inside group)
        const unsigned FULL = 0xFFFFFFFFu;
        float m = o[0];
#pragma unroll
        for (int j = 1; j < 8; j++) m = fmaxf(m, o[j]);
#pragma unroll
        for (int off = 1; off < 8; off <<= 1)
            m = fmaxf(m, __shfl_xor_sync(FULL, m, off));
        float s = 0.f;
#pragma unroll
        for (int j = 0; j < 8; j++) s += __expf(o[j] - m);
#pragma unroll
        for (int off = 1; off < 8; off <<= 1)
            s += __shfl_xor_sync(FULL, s, off);
        float l = m + __logf(s);
        if (valid) {
            float* zo = (float*)zout_v;
            float4 r0 = make_float4(o[0] - l, o[1] - l, o[2] - l, o[3] - l);
            float4 r1 = make_float4(o[4] - l, o[5] - l, o[6] - l, o[7] - l);
            float4* p = reinterpret_cast<float4*>(zo + (size_t)node * NCLASS);
            p[2 * c8]     = r0;
            p[2 * c8 + 1] = r1;
        }
    }
}

// =================================================================
// launch
// =================================================================
extern "C" void kernel_launch(void* const* d_in, const int* in_sizes, int n_in,
                              void* d_out, int out_size)
{
    const float* x   = (const float*)d_in[0];
    const int*   ei  = (const int*)  d_in[1];
    const float* ew  = (const float*)d_in[2];
    const float* W1  = (const float*)d_in[3];
    const float* W2  = (const float*)d_in[4];
    float*       out = (float*)d_out;

    const int n = in_sizes[0] / NFEAT;
    const int e = in_sizes[2];
    const int* src = ei;
    const int* dst = ei + e;

    float*    z0  = nullptr; cudaGetSymbolAddress((void**)&z0,  g_z0);
    __half*   y0  = nullptr; cudaGetSymbolAddress((void**)&y0,  g_y0);
    __half*   ya  = nullptr; cudaGetSymbolAddress((void**)&ya,  g_ya);
    __half*   yb  = nullptr; cudaGetSymbolAddress((void**)&yb,  g_yb);
    int*      rp  = nullptr; cudaGetSymbolAddress((void**)&rp,  g_rowptr);
    int*      cur = nullptr; cudaGetSymbolAddress((void**)&cur, g_cursor);
    int*      bs  = nullptr; cudaGetSymbolAddress((void**)&bs,  g_bsums);
    uint32_t* edg = nullptr; cudaGetSymbolAddress((void**)&edg, g_edges);

    static cudaStream_t sG = nullptr;
    static cudaEvent_t  evF = nullptr, evG = nullptr;
    if (sG == nullptr) {
        cudaStreamCreateWithFlags(&sG, cudaStreamNonBlocking);
        cudaEventCreateWithFlags(&evF, cudaEventDisableTiming);
        cudaEventCreateWithFlags(&evG, cudaEventDisableTiming);
        cudaFuncSetAttribute(gemm_mma,
            cudaFuncAttributeMaxDynamicSharedMemorySize, GM_SMEM);
    }

    // ---- fork: tensor-core GEMM (with fused fp16 cast) on side stream ----
    cudaEventRecord(evF, 0);
    cudaStreamWaitEvent(sG, evF, 0);
    gemm_mma<<<(n + 255) / 256, 256, GM_SMEM, sG>>>(x, W1, W2, z0, y0, n);
    cudaEventRecord(evG, sG);

    // ---- CSR build on capture stream ----
    cudaMemsetAsync(cur, 0, (size_t)n * sizeof(int), 0);
    hist_dst<<<(e + 255) / 256, 256>>>(dst, cur, e);
    int nb = (n + SCAN_BLK - 1) / SCAN_BLK;
    scan1<<<nb, SCAN_BLK>>>(cur, rp, bs, n);
    scan2<<<1, 128>>>(bs, nb);
    scan3<<<(n + 256) / 256, 256>>>(rp, cur, bs, n, e);
    build_edges<<<(e + 255) / 256, 256>>>(src, dst, ew, cur, edg, e);

    // ---- join ----
    cudaStreamWaitEvent(0, evG, 0);

    // ---- APPNP, scaled-fp16 pipeline ----
    // y_t = z_t / 16^t (exact power-of-two scaling)
    const float S = 16.0f;
    const int gblocks = (n * 8 + 255) / 256;   // 4 nodes per warp

    // iter 0: y0 -> y1 (ya)
    gather_nodes<false><<<gblocks, 256>>>(
        edg, rp, y0, y0, z0, ya, 1.0f / S, ALPHA / S, n);

    // iters 1..8: y_t -> y_{t+1}   (t=8 output lands in bufs[0]=ya)
    __half* bufs[2] = { ya, yb };
    float pw = S * S;
    for (int t = 1; t <= 8; t++) {
        __half* zin  = bufs[(t + 1) & 1];
        __half* zout = bufs[t & 1];
        gather_nodes<false><<<gblocks, 256>>>(
            edg, rp, zin, y0, z0, zout, 1.0f / S, ALPHA / pw, n);
        pw *= S;
    }

    // iter 9 (final): input y9 = bufs[0], fp32 z0 injection, fused log_softmax
    float S9 = 1.0f;
    for (int k = 0; k < 9; k++) S9 *= S;
    gather_nodes<true><<<gblocks, 256>>>(
        edg, rp, bufs[0], y0, z0, out, S9, ALPHA, n);
}

// round 15
// speedup vs baseline: 1.4004x; 1.0578x over previous
#include <cuda_runtime.h>
#include <cuda_fp16.h>
#include <cuda_bf16.h>
#include <cstdint>

// ---------------- problem constants ----------------
#define MAXN    100000
#define MAXE    3200000
#define NFEAT   512
#define HID     64
#define NCLASS  64
#define ALPHA   0.1f
#define NITER   10
#define SCAN_BLK 1024

// ---------------- static device scratch ----------------
__device__ float    g_z0[MAXN * NCLASS];   // fp32 base prediction
__device__ __half   g_y0[MAXN * NCLASS];   // fp16 cast of z0
__device__ __half   g_ya[MAXN * NCLASS];   // fp16 scaled z ping
__device__ __half   g_yb[MAXN * NCLASS];   // fp16 scaled z pong
__device__ int      g_rowptr[MAXN + 1];
__device__ int      g_cursor[MAXN];
__device__ int      g_bsums[128];
__device__ int      g_dbin[256];           // degree histogram bins
__device__ int      g_perm[MAXN];          // degree-sorted node permutation
__device__ uint32_t g_edges[MAXE];         // packed: src(17b) << 15 | w_q15(15b)

// ================= mma.sync helpers (baseline sm_80+, works on sm_103) ====
__device__ __forceinline__ uint32_t smem_u32(const void* p) {
    uint32_t a;
    asm("{ .reg .u64 t; cvta.to.shared.u64 t, %1; cvt.u32.u64 %0, t; }"
        : "=r"(a) : "l"(p));
    return a;
}
__device__ __forceinline__ void ldsm_x4(uint32_t* r, uint32_t addr) {
    asm volatile("ldmatrix.sync.aligned.m8n8.x4.shared.b16 {%0,%1,%2,%3}, [%4];"
                 : "=r"(r[0]), "=r"(r[1]), "=r"(r[2]), "=r"(r[3]) : "r"(addr));
}
__device__ __forceinline__ void ldsm_x4_t(uint32_t* r, uint32_t addr) {
    asm volatile("ldmatrix.sync.aligned.m8n8.x4.trans.shared.b16 {%0,%1,%2,%3}, [%4];"
                 : "=r"(r[0]), "=r"(r[1]), "=r"(r[2]), "=r"(r[3]) : "r"(addr));
}
__device__ __forceinline__ void mma_bf16(
    float* d, const uint32_t* a, const uint32_t* b)
{
    asm volatile(
        "mma.sync.aligned.m16n8k16.row.col.f32.bf16.bf16.f32 "
        "{%0,%1,%2,%3}, {%4,%5,%6,%7}, {%8,%9}, {%0,%1,%2,%3};"
        : "+f"(d[0]), "+f"(d[1]), "+f"(d[2]), "+f"(d[3])
        : "r"(a[0]), "r"(a[1]), "r"(a[2]), "r"(a[3]), "r"(b[0]), "r"(b[1]));
}
__device__ __forceinline__ uint32_t pkbf2(float a, float b) {
    __nv_bfloat162 h = __floats2bfloat162_rn(a, b);
    return *reinterpret_cast<uint32_t*>(&h);
}

// =================================================================
// mma.sync fused GEMM: z0 = relu(x @ W1) @ W2, bf16 hi/lo 3-term split.
// Epilogue also emits y0 = fp16(z0) (fused cvt).
// =================================================================
#define GM_AHI 0
#define GM_ALO 36864
#define GM_BHI 73728
#define GM_BLO 82944
#define GM_SMEM 92160

__global__ __launch_bounds__(256) void gemm_mma(
    const float* __restrict__ X, const float* __restrict__ W1,
    const float* __restrict__ W2, float* __restrict__ Z0,
    __half* __restrict__ Y0, int n)
{
    extern __shared__ char smc[];
    const uint32_t sb = smem_u32(smc);
    const int tid = threadIdx.x;
    const int wid = tid >> 5;
    const int l   = tid & 31;
    const int bm  = blockIdx.x * 256;
    const int wr  = wid * 32;

    const int arow = (l & 7) + ((l >> 3) & 1) * 8;
    const uint32_t akb = ((l >> 4) & 1) * 16;
    const uint32_t aoff0 = (uint32_t)(wr + arow) * 144 + akb;
    const uint32_t aoff1 = (uint32_t)(wr + 16 + arow) * 144 + akb;
    const uint32_t boff  = (uint32_t)arow * 144 + akb;

    float acc[2][8][4];
#pragma unroll
    for (int am = 0; am < 2; am++)
#pragma unroll
        for (int na = 0; na < 8; na++)
#pragma unroll
            for (int q = 0; q < 4; q++) acc[am][na][q] = 0.f;

    for (int c = 0; c < 8; c++) {
#pragma unroll
        for (int it = 0; it < 16; it++) {
            int idx = it * 256 + tid;
            int r   = idx >> 4;
            int c4  = idx & 15;
            int row = bm + r;
            float4 v = make_float4(0.f, 0.f, 0.f, 0.f);
            if (row < n)
                v = *reinterpret_cast<const float4*>(X + (size_t)row * NFEAT + c * 64 + c4 * 4);
            uint32_t h0 = pkbf2(v.x, v.y), h1 = pkbf2(v.z, v.w);
            __nv_bfloat162 bh0 = *reinterpret_cast<__nv_bfloat162*>(&h0);
            __nv_bfloat162 bh1 = *reinterpret_cast<__nv_bfloat162*>(&h1);
            float2 f0 = __bfloat1622float2(bh0);
            float2 f1 = __bfloat1622float2(bh1);
            uint32_t l0 = pkbf2(v.x - f0.x, v.y - f0.y);
            uint32_t l1 = pkbf2(v.z - f1.x, v.w - f1.y);
            uint32_t off = (uint32_t)r * 144 + c4 * 8;
            *reinterpret_cast<uint2*>(smc + GM_AHI + off) = make_uint2(h0, h1);
            *reinterpret_cast<uint2*>(smc + GM_ALO + off) = make_uint2(l0, l1);
        }
#pragma unroll
        for (int it = 0; it < 4; it++) {
            int idx = it * 256 + tid;
            int k   = idx >> 4;
            int c4  = idx & 15;
            float4 v = *reinterpret_cast<const float4*>(W1 + (size_t)(c * 64 + k) * HID + c4 * 4);
            uint32_t h0 = pkbf2(v.x, v.y), h1 = pkbf2(v.z, v.w);
            __nv_bfloat162 bh0 = *reinterpret_cast<__nv_bfloat162*>(&h0);
            __nv_bfloat162 bh1 = *reinterpret_cast<__nv_bfloat162*>(&h1);
            float2 f0 = __bfloat1622float2(bh0);
            float2 f1 = __bfloat1622float2(bh1);
            uint32_t l0 = pkbf2(v.x - f0.x, v.y - f0.y);
            uint32_t l1 = pkbf2(v.z - f1.x, v.w - f1.y);
            uint32_t off = (uint32_t)k * 144 + c4 * 8;
            *reinterpret_cast<uint2*>(smc + GM_BHI + off) = make_uint2(h0, h1);
            *reinterpret_cast<uint2*>(smc + GM_BLO + off) = make_uint2(l0, l1);
        }
        __syncthreads();

#pragma unroll
        for (int s = 0; s < 4; s++) {
            uint32_t ah0[4], ah1[4], al0[4], al1[4];
            ldsm_x4(ah0, sb + GM_AHI + aoff0 + s * 32);
            ldsm_x4(ah1, sb + GM_AHI + aoff1 + s * 32);
            ldsm_x4(al0, sb + GM_ALO + aoff0 + s * 32);
            ldsm_x4(al1, sb + GM_ALO + aoff1 + s * 32);
            uint32_t bh[8][2], bl[8][2];
#pragma unroll
            for (int p = 0; p < 4; p++) {
                uint32_t r4[4];
                ldsm_x4_t(r4, sb + GM_BHI + s * 2304 + p * 32 + boff);
                bh[2 * p][0] = r4[0]; bh[2 * p][1] = r4[1];
                bh[2 * p + 1][0] = r4[2]; bh[2 * p + 1][1] = r4[3];
                ldsm_x4_t(r4, sb + GM_BLO + s * 2304 + p * 32 + boff);
                bl[2 * p][0] = r4[0]; bl[2 * p][1] = r4[1];
                bl[2 * p + 1][0] = r4[2]; bl[2 * p + 1][1] = r4[3];
            }
#pragma unroll
            for (int na = 0; na < 8; na++) {
                mma_bf16(acc[0][na], ah0, bh[na]);
                mma_bf16(acc[1][na], ah1, bh[na]);
                mma_bf16(acc[0][na], al0, bh[na]);
                mma_bf16(acc[1][na], al1, bh[na]);
                mma_bf16(acc[0][na], ah0, bl[na]);
                mma_bf16(acc[1][na], ah1, bl[na]);
            }
        }
        __syncthreads();
    }

    // ---- phase 2 ----
    uint32_t a2h[2][4][4], a2l[2][4][4];
#pragma unroll
    for (int am = 0; am < 2; am++)
#pragma unroll
        for (int s = 0; s < 4; s++) {
            float v00 = fmaxf(acc[am][2 * s][0], 0.f);
            float v01 = fmaxf(acc[am][2 * s][1], 0.f);
            float v02 = fmaxf(acc[am][2 * s][2], 0.f);
            float v03 = fmaxf(acc[am][2 * s][3], 0.f);
            float v10 = fmaxf(acc[am][2 * s + 1][0], 0.f);
            float v11 = fmaxf(acc[am][2 * s + 1][1], 0.f);
            float v12 = fmaxf(acc[am][2 * s + 1][2], 0.f);
            float v13 = fmaxf(acc[am][2 * s + 1][3], 0.f);
            uint32_t h;
            h = pkbf2(v00, v01); a2h[am][s][0] = h;
            { __nv_bfloat162 b = *reinterpret_cast<__nv_bfloat162*>(&h); float2 f = __bfloat1622float2(b);
              a2l[am][s][0] = pkbf2(v00 - f.x, v01 - f.y); }
            h = pkbf2(v02, v03); a2h[am][s][1] = h;
            { __nv_bfloat162 b = *reinterpret_cast<__nv_bfloat162*>(&h); float2 f = __bfloat1622float2(b);
              a2l[am][s][1] = pkbf2(v02 - f.x, v03 - f.y); }
            h = pkbf2(v10, v11); a2h[am][s][2] = h;
            { __nv_bfloat162 b = *reinterpret_cast<__nv_bfloat162*>(&h); float2 f = __bfloat1622float2(b);
              a2l[am][s][2] = pkbf2(v10 - f.x, v11 - f.y); }
            h = pkbf2(v12, v13); a2h[am][s][3] = h;
            { __nv_bfloat162 b = *reinterpret_cast<__nv_bfloat162*>(&h); float2 f = __bfloat1622float2(b);
              a2l[am][s][3] = pkbf2(v12 - f.x, v13 - f.y); }
        }

#pragma unroll
    for (int am = 0; am < 2; am++)
#pragma unroll
        for (int na = 0; na < 8; na++)
#pragma unroll
            for (int q = 0; q < 4; q++) acc[am][na][q] = 0.f;

#pragma unroll
    for (int it = 0; it < 4; it++) {
        int idx = it * 256 + tid;
        int k   = idx >> 4;
        int c4  = idx & 15;
        float4 v = *reinterpret_cast<const float4*>(W2 + (size_t)k * NCLASS + c4 * 4);
        uint32_t h0 = pkbf2(v.x, v.y), h1 = pkbf2(v.z, v.w);
        __nv_bfloat162 bh0 = *reinterpret_cast<__nv_bfloat162*>(&h0);
        __nv_bfloat162 bh1 = *reinterpret_cast<__nv_bfloat162*>(&h1);
        float2 f0 = __bfloat1622float2(bh0);
        float2 f1 = __bfloat1622float2(bh1);
        uint32_t l0 = pkbf2(v.x - f0.x, v.y - f0.y);
        uint32_t l1 = pkbf2(v.z - f1.x, v.w - f1.y);
        uint32_t off = (uint32_t)k * 144 + c4 * 8;
        *reinterpret_cast<uint2*>(smc + GM_BHI + off) = make_uint2(h0, h1);
        *reinterpret_cast<uint2*>(smc + GM_BLO + off) = make_uint2(l0, l1);
    }
    __syncthreads();

#pragma unroll
    for (int s = 0; s < 4; s++) {
        uint32_t bh[8][2], bl[8][2];
#pragma unroll
        for (int p = 0; p < 4; p++) {
            uint32_t r4[4];
            ldsm_x4_t(r4, sb + GM_BHI + s * 2304 + p * 32 + boff);
            bh[2 * p][0] = r4[0]; bh[2 * p][1] = r4[1];
            bh[2 * p + 1][0] = r4[2]; bh[2 * p + 1][1] = r4[3];
            ldsm_x4_t(r4, sb + GM_BLO + s * 2304 + p * 32 + boff);
            bl[2 * p][0] = r4[0]; bl[2 * p][1] = r4[1];
            bl[2 * p + 1][0] = r4[2]; bl[2 * p + 1][1] = r4[3];
        }
#pragma unroll
        for (int na = 0; na < 8; na++) {
            mma_bf16(acc[0][na], a2h[0][s], bh[na]);
            mma_bf16(acc[1][na], a2h[1][s], bh[na]);
            mma_bf16(acc[0][na], a2l[0][s], bh[na]);
            mma_bf16(acc[1][na], a2l[1][s], bh[na]);
            mma_bf16(acc[0][na], a2h[0][s], bl[na]);
            mma_bf16(acc[1][na], a2h[1][s], bl[na]);
        }
    }

    // store z0 (fp32) + y0 (fp16, fused cast)
#pragma unroll
    for (int am = 0; am < 2; am++) {
        int r0 = bm + wr + am * 16 + (l >> 2);
        int col = (l & 3) * 2;
#pragma unroll
        for (int na = 0; na < 8; na++) {
            if (r0 < n) {
                *reinterpret_cast<float2*>(Z0 + (size_t)r0 * NCLASS + na * 8 + col) =
                    make_float2(acc[am][na][0], acc[am][na][1]);
                __half2 hh = __floats2half2_rn(acc[am][na][0], acc[am][na][1]);
                *reinterpret_cast<__half2*>(Y0 + (size_t)r0 * NCLASS + na * 8 + col) = hh;
            }
            if (r0 + 8 < n) {
                *reinterpret_cast<float2*>(Z0 + (size_t)(r0 + 8) * NCLASS + na * 8 + col) =
                    make_float2(acc[am][na][2], acc[am][na][3]);
                __half2 hh = __floats2half2_rn(acc[am][na][2], acc[am][na][3]);
                *reinterpret_cast<__half2*>(Y0 + (size_t)(r0 + 8) * NCLASS + na * 8 + col) = hh;
            }
        }
    }
}

// =================================================================
// CSR construction (3-kernel scan — proven ~12us)
// =================================================================
__global__ __launch_bounds__(256) void hist_dst(
    const int* __restrict__ dst, int* __restrict__ cnt, int e)
{
    int i = blockIdx.x * 256 + threadIdx.x;
    if (i < e) atomicAdd(&cnt[dst[i]], 1);
}

__global__ __launch_bounds__(SCAN_BLK) void scan1(
    const int* __restrict__ cnt, int* __restrict__ rowptr,
    int* __restrict__ bsums, int n)
{
    __shared__ int sh[SCAN_BLK];
    int t = threadIdx.x;
    int i = blockIdx.x * SCAN_BLK + t;
    int v = (i < n) ? cnt[i] : 0;
    sh[t] = v;
    __syncthreads();
#pragma unroll
    for (int off = 1; off < SCAN_BLK; off <<= 1) {
        int x = (t >= off) ? sh[t - off] : 0;
        __syncthreads();
        sh[t] += x;
        __syncthreads();
    }
    int incl = sh[t];
    if (i < n) rowptr[i] = incl - v;
    if (t == SCAN_BLK - 1) bsums[blockIdx.x] = incl;
}

__global__ __launch_bounds__(128) void scan2(int* __restrict__ bsums, int nb)
{
    __shared__ int sh[128];
    int t = threadIdx.x;
    int v = (t < nb) ? bsums[t] : 0;
    sh[t] = v;
    __syncthreads();
#pragma unroll
    for (int off = 1; off < 128; off <<= 1) {
        int x = (t >= off) ? sh[t - off] : 0;
        __syncthreads();
        sh[t] += x;
        __syncthreads();
    }
    if (t < nb) bsums[t] = sh[t] - v;
}

__global__ __launch_bounds__(256) void scan3(
    int* __restrict__ rowptr, int* __restrict__ cursor,
    const int* __restrict__ bsums, int n, int e)
{
    int i = blockIdx.x * 256 + threadIdx.x;
    if (i < n) {
        int v = rowptr[i] + bsums[i >> 10];
        rowptr[i] = v;
        cursor[i] = v;
    }
    if (i == n) rowptr[n] = e;
}

// pack: src (17 bits, <<15) | weight q15 (15 bits)
__global__ __launch_bounds__(256) void build_edges(
    const int* __restrict__ src, const int* __restrict__ dst,
    const float* __restrict__ ew, int* __restrict__ cursor,
    uint32_t* __restrict__ edges, int e)
{
    int i = blockIdx.x * 256 + threadIdx.x;
    if (i < e) {
        int d = dst[i];
        int pos = atomicAdd(&cursor[d], 1);
        int q = __float2int_rn(ew[i] * 32768.0f);
        if (q > 32767) q = 32767;
        if (q < 0) q = 0;
        edges[pos] = ((uint32_t)src[i] << 15) | (uint32_t)q;
    }
}

// ---- degree-sorted permutation (descending degree) ----
__global__ __launch_bounds__(256) void deg_hist(
    const int* __restrict__ rowptr, int* __restrict__ dbin, int n)
{
    int i = blockIdx.x * 256 + threadIdx.x;
    if (i < n) {
        int deg = rowptr[i + 1] - rowptr[i];
        if (deg > 255) deg = 255;
        atomicAdd(&dbin[deg], 1);
    }
}

// exclusive scan over REVERSED bins -> descending-degree offsets
__global__ __launch_bounds__(256) void scan_bins(int* __restrict__ dbin)
{
    __shared__ int sh[256];
    int t = threadIdx.x;
    int v = dbin[255 - t];
    sh[t] = v;
    __syncthreads();
#pragma unroll
    for (int off = 1; off < 256; off <<= 1) {
        int x = (t >= off) ? sh[t - off] : 0;
        __syncthreads();
        sh[t] += x;
        __syncthreads();
    }
    dbin[255 - t] = sh[t] - v;   // exclusive offset for degree (255-t)
}

__global__ __launch_bounds__(256) void perm_scatter(
    const int* __restrict__ rowptr, int* __restrict__ dbin,
    int* __restrict__ perm, int n)
{
    int i = blockIdx.x * 256 + threadIdx.x;
    if (i < n) {
        int deg = rowptr[i + 1] - rowptr[i];
        if (deg > 255) deg = 255;
        int pos = atomicAdd(&dbin[deg], 1);
        perm[pos] = i;
    }
}

// =================================================================
// gather: FOUR nodes per warp (8 lanes each), nodes taken from the
// degree-sorted permutation so the 4 degrees per warp are ~equal.
// 2-deep unroll (8 rows in flight/warp). Packed 4B edges.
// =================================================================
__device__ __forceinline__ void load_row8_h(
    const __half* zin, uint32_t node, int c8, float* v)
{
    float4 raw = __ldg(reinterpret_cast<const float4*>(zin + (size_t)node * NCLASS) + c8);
    const __half2* h = reinterpret_cast<const __half2*>(&raw);
#pragma unroll
    for (int j = 0; j < 4; j++) {
        float2 f = __half22float2(h[j]);
        v[2 * j]     = f.x;
        v[2 * j + 1] = f.y;
    }
}
__device__ __forceinline__ void load_row8_f(
    const float* zin, int node, int c8, float* v)
{
    const float4* p = reinterpret_cast<const float4*>(zin + (size_t)node * NCLASS);
    float4 a = __ldg(p + 2 * c8);
    float4 b = __ldg(p + 2 * c8 + 1);
    v[0] = a.x; v[1] = a.y; v[2] = a.z; v[3] = a.w;
    v[4] = b.x; v[5] = b.y; v[6] = b.z; v[7] = b.w;
}

#define WQ 3.0517578125e-5f   // 1/32768

template<bool LAST>
__global__ __launch_bounds__(256) void gather_nodes(
    const uint32_t* __restrict__ edges, const int* __restrict__ rowptr,
    const int* __restrict__ perm,
    const __half* __restrict__ zin, const __half* __restrict__ y0,
    const float* __restrict__ z0, void* __restrict__ zout_v,
    float c1, float c0, int n)
{
    int lane = threadIdx.x & 31;
    int warp = (blockIdx.x * 256 + threadIdx.x) >> 5;
    int pidx = warp * 4 + (lane >> 3);   // 4 permutation slots per warp
    int c8   = lane & 7;

    bool valid = (pidx < n);
    int node = valid ? __ldg(&perm[pidx]) : 0;
    int beg = 0, end = 0;
    if (valid) {
        beg = __ldg(&rowptr[node]);
        end = __ldg(&rowptr[node + 1]);
    }

    float acc[8];
#pragma unroll
    for (int j = 0; j < 8; j++) acc[j] = 0.f;

    int i = beg;
    for (; i + 1 < end; i += 2) {
        uint32_t e0 = __ldg(&edges[i]);
        uint32_t e1 = __ldg(&edges[i + 1]);
        float v0[8], v1[8];
        load_row8_h(zin, e0 >> 15, c8, v0);
        load_row8_h(zin, e1 >> 15, c8, v1);
        float w0 = (float)(e0 & 0x7FFFu) * WQ;
        float w1 = (float)(e1 & 0x7FFFu) * WQ;
#pragma unroll
        for (int j = 0; j < 8; j++) acc[j] = fmaf(w0, v0[j], acc[j]);
#pragma unroll
        for (int j = 0; j < 8; j++) acc[j] = fmaf(w1, v1[j], acc[j]);
    }
    if (i < end) {
        uint32_t e0 = __ldg(&edges[i]);
        float v0[8];
        load_row8_h(zin, e0 >> 15, c8, v0);
        float w0 = (float)(e0 & 0x7FFFu) * WQ;
#pragma unroll
        for (int j = 0; j < 8; j++) acc[j] = fmaf(w0, v0[j], acc[j]);
    }

    float z0v[8];
    if (LAST) load_row8_f(z0, node, c8, z0v);
    else      load_row8_h(y0, (uint32_t)node, c8, z0v);
    float o[8];
#pragma unroll
    for (int j = 0; j < 8; j++) o[j] = fmaf(c0, z0v[j], c1 * acc[j]);

    if (!LAST) {
        if (valid) {
            __half2 h[4];
#pragma unroll
            for (int j = 0; j < 4; j++)
                h[j] = __floats2half2_rn(o[2 * j], o[2 * j + 1]);
            __half* zo = (__half*)zout_v;
            *(reinterpret_cast<float4*>(zo + (size_t)node * NCLASS) + c8) =
                *reinterpret_cast<float4*>(h);
        }
    } else {
        const unsigned FULL = 0xFFFFFFFFu;
        float m = o[0];
#pragma unroll
        for (int j = 1; j < 8; j++) m = fmaxf(m, o[j]);
#pragma unroll
        for (int off = 1; off < 8; off <<= 1)
            m = fmaxf(m, __shfl_xor_sync(FULL, m, off));
        float s = 0.f;
#pragma unroll
        for (int j = 0; j < 8; j++) s += __expf(o[j] - m);
#pragma unroll
        for (int off = 1; off < 8; off <<= 1)
            s += __shfl_xor_sync(FULL, s, off);
        float l = m + __logf(s);
        if (valid) {
            float* zo = (float*)zout_v;
            float4 r0 = make_float4(o[0] - l, o[1] - l, o[2] - l, o[3] - l);
            float4 r1 = make_float4(o[4] - l, o[5] - l, o[6] - l, o[7] - l);
            float4* p = reinterpret_cast<float4*>(zo + (size_t)node * NCLASS);
            p[2 * c8]     = r0;
            p[2 * c8 + 1] = r1;
        }
    }
}

// =================================================================
// launch
// =================================================================
extern "C" void kernel_launch(void* const* d_in, const int* in_sizes, int n_in,
                              void* d_out, int out_size)
{
    const float* x   = (const float*)d_in[0];
    const int*   ei  = (const int*)  d_in[1];
    const float* ew  = (const float*)d_in[2];
    const float* W1  = (const float*)d_in[3];
    const float* W2  = (const float*)d_in[4];
    float*       out = (float*)d_out;

    const int n = in_sizes[0] / NFEAT;
    const int e = in_sizes[2];
    const int* src = ei;
    const int* dst = ei + e;

    float*    z0  = nullptr; cudaGetSymbolAddress((void**)&z0,  g_z0);
    __half*   y0  = nullptr; cudaGetSymbolAddress((void**)&y0,  g_y0);
    __half*   ya  = nullptr; cudaGetSymbolAddress((void**)&ya,  g_ya);
    __half*   yb  = nullptr; cudaGetSymbolAddress((void**)&yb,  g_yb);
    int*      rp  = nullptr; cudaGetSymbolAddress((void**)&rp,  g_rowptr);
    int*      cur = nullptr; cudaGetSymbolAddress((void**)&cur, g_cursor);
    int*      bs  = nullptr; cudaGetSymbolAddress((void**)&bs,  g_bsums);
    int*      db  = nullptr; cudaGetSymbolAddress((void**)&db,  g_dbin);
    int*      pm  = nullptr; cudaGetSymbolAddress((void**)&pm,  g_perm);
    uint32_t* edg = nullptr; cudaGetSymbolAddress((void**)&edg, g_edges);

    static cudaStream_t sG = nullptr;
    static cudaEvent_t  evF = nullptr, evG = nullptr;
    if (sG == nullptr) {
        cudaStreamCreateWithFlags(&sG, cudaStreamNonBlocking);
        cudaEventCreateWithFlags(&evF, cudaEventDisableTiming);
        cudaEventCreateWithFlags(&evG, cudaEventDisableTiming);
        cudaFuncSetAttribute(gemm_mma,
            cudaFuncAttributeMaxDynamicSharedMemorySize, GM_SMEM);
    }

    // ---- fork: tensor-core GEMM (with fused fp16 cast) on side stream ----
    cudaEventRecord(evF, 0);
    cudaStreamWaitEvent(sG, evF, 0);
    gemm_mma<<<(n + 255) / 256, 256, GM_SMEM, sG>>>(x, W1, W2, z0, y0, n);
    cudaEventRecord(evG, sG);

    // ---- CSR build + degree-sorted perm on capture stream ----
    cudaMemsetAsync(cur, 0, (size_t)n * sizeof(int), 0);
    cudaMemsetAsync(db, 0, 256 * sizeof(int), 0);
    hist_dst<<<(e + 255) / 256, 256>>>(dst, cur, e);
    int nb = (n + SCAN_BLK - 1) / SCAN_BLK;
    scan1<<<nb, SCAN_BLK>>>(cur, rp, bs, n);
    scan2<<<1, 128>>>(bs, nb);
    scan3<<<(n + 256) / 256, 256>>>(rp, cur, bs, n, e);
    build_edges<<<(e + 255) / 256, 256>>>(src, dst, ew, cur, edg, e);
    deg_hist<<<(n + 255) / 256, 256>>>(rp, db, n);
    scan_bins<<<1, 256>>>(db);
    perm_scatter<<<(n + 255) / 256, 256>>>(rp, db, pm, n);

    // ---- join ----
    cudaStreamWaitEvent(0, evG, 0);

    // ---- APPNP, scaled-fp16 pipeline ----
    const float S = 16.0f;
    const int gblocks = (n * 8 + 255) / 256;   // 4 nodes per warp

    gather_nodes<false><<<gblocks, 256>>>(
        edg, rp, pm, y0, y0, z0, ya, 1.0f / S, ALPHA / S, n);

    __half* bufs[2] = { ya, yb };
    float pw = S * S;
    for (int t = 1; t <= 8; t++) {
        __half* zin  = bufs[(t + 1) & 1];
        __half* zout = bufs[t & 1];
        gather_nodes<false><<<gblocks, 256>>>(
            edg, rp, pm, zin, y0, z0, zout, 1.0f / S, ALPHA / pw, n);
        pw *= S;
    }

    float S9 = 1.0f;
    for (int k = 0; k < 9; k++) S9 *= S;
    gather_nodes<true><<<gblocks, 256>>>(
        edg, rp, pm, bufs[0], y0, z0, out, S9, ALPHA, n);
}

// round 16
// speedup vs baseline: 1.4234x; 1.0165x over previous
#include <cuda_runtime.h>
#include <cuda_fp16.h>
#include <cuda_bf16.h>
#include <cstdint>

// ---------------- problem constants ----------------
#define MAXN    100000
#define MAXE    3200000
#define NFEAT   512
#define HID     64
#define NCLASS  64
#define ALPHA   0.1f
#define NITER   10
#define SCAN_BLK 1024

// ---------------- static device scratch ----------------
__device__ float    g_z0[MAXN * NCLASS];   // fp32 base prediction
__device__ __half   g_y0[MAXN * NCLASS];   // fp16 cast of z0
__device__ __half   g_ya[MAXN * NCLASS];   // fp16 scaled z ping
__device__ __half   g_yb[MAXN * NCLASS];   // fp16 scaled z pong
__device__ int      g_rowptr[MAXN + 1];
__device__ int      g_cursor[MAXN];
__device__ int      g_bsums[128];
__device__ int      g_dbin[256];           // degree histogram bins
__device__ int      g_perm[MAXN];          // degree-sorted node permutation
__device__ uint32_t g_edges[MAXE];         // packed: src(17b) << 15 | w_q15(15b)

// ================= mma.sync helpers (baseline sm_80+, works on sm_103) ====
__device__ __forceinline__ uint32_t smem_u32(const void* p) {
    uint32_t a;
    asm("{ .reg .u64 t; cvta.to.shared.u64 t, %1; cvt.u32.u64 %0, t; }"
        : "=r"(a) : "l"(p));
    return a;
}
__device__ __forceinline__ void ldsm_x4(uint32_t* r, uint32_t addr) {
    asm volatile("ldmatrix.sync.aligned.m8n8.x4.shared.b16 {%0,%1,%2,%3}, [%4];"
                 : "=r"(r[0]), "=r"(r[1]), "=r"(r[2]), "=r"(r[3]) : "r"(addr));
}
__device__ __forceinline__ void ldsm_x4_t(uint32_t* r, uint32_t addr) {
    asm volatile("ldmatrix.sync.aligned.m8n8.x4.trans.shared.b16 {%0,%1,%2,%3}, [%4];"
                 : "=r"(r[0]), "=r"(r[1]), "=r"(r[2]), "=r"(r[3]) : "r"(addr));
}
__device__ __forceinline__ void mma_bf16(
    float* d, const uint32_t* a, const uint32_t* b)
{
    asm volatile(
        "mma.sync.aligned.m16n8k16.row.col.f32.bf16.bf16.f32 "
        "{%0,%1,%2,%3}, {%4,%5,%6,%7}, {%8,%9}, {%0,%1,%2,%3};"
        : "+f"(d[0]), "+f"(d[1]), "+f"(d[2]), "+f"(d[3])
        : "r"(a[0]), "r"(a[1]), "r"(a[2]), "r"(a[3]), "r"(b[0]), "r"(b[1]));
}
__device__ __forceinline__ uint32_t pkbf2(float a, float b) {
    __nv_bfloat162 h = __floats2bfloat162_rn(a, b);
    return *reinterpret_cast<uint32_t*>(&h);
}

// =================================================================
// mma.sync fused GEMM: z0 = relu(x @ W1) @ W2, bf16 hi/lo 3-term split.
// Epilogue also emits y0 = fp16(z0) (fused cvt).
// =================================================================
#define GM_AHI 0
#define GM_ALO 36864
#define GM_BHI 73728
#define GM_BLO 82944
#define GM_SMEM 92160

__global__ __launch_bounds__(256) void gemm_mma(
    const float* __restrict__ X, const float* __restrict__ W1,
    const float* __restrict__ W2, float* __restrict__ Z0,
    __half* __restrict__ Y0, int n)
{
    extern __shared__ char smc[];
    const uint32_t sb = smem_u32(smc);
    const int tid = threadIdx.x;
    const int wid = tid >> 5;
    const int l   = tid & 31;
    const int bm  = blockIdx.x * 256;
    const int wr  = wid * 32;

    const int arow = (l & 7) + ((l >> 3) & 1) * 8;
    const uint32_t akb = ((l >> 4) & 1) * 16;
    const uint32_t aoff0 = (uint32_t)(wr + arow) * 144 + akb;
    const uint32_t aoff1 = (uint32_t)(wr + 16 + arow) * 144 + akb;
    const uint32_t boff  = (uint32_t)arow * 144 + akb;

    float acc[2][8][4];
#pragma unroll
    for (int am = 0; am < 2; am++)
#pragma unroll
        for (int na = 0; na < 8; na++)
#pragma unroll
            for (int q = 0; q < 4; q++) acc[am][na][q] = 0.f;

    for (int c = 0; c < 8; c++) {
#pragma unroll
        for (int it = 0; it < 16; it++) {
            int idx = it * 256 + tid;
            int r   = idx >> 4;
            int c4  = idx & 15;
            int row = bm + r;
            float4 v = make_float4(0.f, 0.f, 0.f, 0.f);
            if (row < n)
                v = *reinterpret_cast<const float4*>(X + (size_t)row * NFEAT + c * 64 + c4 * 4);
            uint32_t h0 = pkbf2(v.x, v.y), h1 = pkbf2(v.z, v.w);
            __nv_bfloat162 bh0 = *reinterpret_cast<__nv_bfloat162*>(&h0);
            __nv_bfloat162 bh1 = *reinterpret_cast<__nv_bfloat162*>(&h1);
            float2 f0 = __bfloat1622float2(bh0);
            float2 f1 = __bfloat1622float2(bh1);
            uint32_t l0 = pkbf2(v.x - f0.x, v.y - f0.y);
            uint32_t l1 = pkbf2(v.z - f1.x, v.w - f1.y);
            uint32_t off = (uint32_t)r * 144 + c4 * 8;
            *reinterpret_cast<uint2*>(smc + GM_AHI + off) = make_uint2(h0, h1);
            *reinterpret_cast<uint2*>(smc + GM_ALO + off) = make_uint2(l0, l1);
        }
#pragma unroll
        for (int it = 0; it < 4; it++) {
            int idx = it * 256 + tid;
            int k   = idx >> 4;
            int c4  = idx & 15;
            float4 v = *reinterpret_cast<const float4*>(W1 + (size_t)(c * 64 + k) * HID + c4 * 4);
            uint32_t h0 = pkbf2(v.x, v.y), h1 = pkbf2(v.z, v.w);
            __nv_bfloat162 bh0 = *reinterpret_cast<__nv_bfloat162*>(&h0);
            __nv_bfloat162 bh1 = *reinterpret_cast<__nv_bfloat162*>(&h1);
            float2 f0 = __bfloat1622float2(bh0);
            float2 f1 = __bfloat1622float2(bh1);
            uint32_t l0 = pkbf2(v.x - f0.x, v.y - f0.y);
            uint32_t l1 = pkbf2(v.z - f1.x, v.w - f1.y);
            uint32_t off = (uint32_t)k * 144 + c4 * 8;
            *reinterpret_cast<uint2*>(smc + GM_BHI + off) = make_uint2(h0, h1);
            *reinterpret_cast<uint2*>(smc + GM_BLO + off) = make_uint2(l0, l1);
        }
        __syncthreads();

#pragma unroll
        for (int s = 0; s < 4; s++) {
            uint32_t ah0[4], ah1[4], al0[4], al1[4];
            ldsm_x4(ah0, sb + GM_AHI + aoff0 + s * 32);
            ldsm_x4(ah1, sb + GM_AHI + aoff1 + s * 32);
            ldsm_x4(al0, sb + GM_ALO + aoff0 + s * 32);
            ldsm_x4(al1, sb + GM_ALO + aoff1 + s * 32);
            uint32_t bh[8][2], bl[8][2];
#pragma unroll
            for (int p = 0; p < 4; p++) {
                uint32_t r4[4];
                ldsm_x4_t(r4, sb + GM_BHI + s * 2304 + p * 32 + boff);
                bh[2 * p][0] = r4[0]; bh[2 * p][1] = r4[1];
                bh[2 * p + 1][0] = r4[2]; bh[2 * p + 1][1] = r4[3];
                ldsm_x4_t(r4, sb + GM_BLO + s * 2304 + p * 32 + boff);
                bl[2 * p][0] = r4[0]; bl[2 * p][1] = r4[1];
                bl[2 * p + 1][0] = r4[2]; bl[2 * p + 1][1] = r4[3];
            }
#pragma unroll
            for (int na = 0; na < 8; na++) {
                mma_bf16(acc[0][na], ah0, bh[na]);
                mma_bf16(acc[1][na], ah1, bh[na]);
                mma_bf16(acc[0][na], al0, bh[na]);
                mma_bf16(acc[1][na], al1, bh[na]);
                mma_bf16(acc[0][na], ah0, bl[na]);
                mma_bf16(acc[1][na], ah1, bl[na]);
            }
        }
        __syncthreads();
    }

    // ---- phase 2 ----
    uint32_t a2h[2][4][4], a2l[2][4][4];
#pragma unroll
    for (int am = 0; am < 2; am++)
#pragma unroll
        for (int s = 0; s < 4; s++) {
            float v00 = fmaxf(acc[am][2 * s][0], 0.f);
            float v01 = fmaxf(acc[am][2 * s][1], 0.f);
            float v02 = fmaxf(acc[am][2 * s][2], 0.f);
            float v03 = fmaxf(acc[am][2 * s][3], 0.f);
            float v10 = fmaxf(acc[am][2 * s + 1][0], 0.f);
            float v11 = fmaxf(acc[am][2 * s + 1][1], 0.f);
            float v12 = fmaxf(acc[am][2 * s + 1][2], 0.f);
            float v13 = fmaxf(acc[am][2 * s + 1][3], 0.f);
            uint32_t h;
            h = pkbf2(v00, v01); a2h[am][s][0] = h;
            { __nv_bfloat162 b = *reinterpret_cast<__nv_bfloat162*>(&h); float2 f = __bfloat1622float2(b);
              a2l[am][s][0] = pkbf2(v00 - f.x, v01 - f.y); }
            h = pkbf2(v02, v03); a2h[am][s][1] = h;
            { __nv_bfloat162 b = *reinterpret_cast<__nv_bfloat162*>(&h); float2 f = __bfloat1622float2(b);
              a2l[am][s][1] = pkbf2(v02 - f.x, v03 - f.y); }
            h = pkbf2(v10, v11); a2h[am][s][2] = h;
            { __nv_bfloat162 b = *reinterpret_cast<__nv_bfloat162*>(&h); float2 f = __bfloat1622float2(b);
              a2l[am][s][2] = pkbf2(v10 - f.x, v11 - f.y); }
            h = pkbf2(v12, v13); a2h[am][s][3] = h;
            { __nv_bfloat162 b = *reinterpret_cast<__nv_bfloat162*>(&h); float2 f = __bfloat1622float2(b);
              a2l[am][s][3] = pkbf2(v12 - f.x, v13 - f.y); }
        }

#pragma unroll
    for (int am = 0; am < 2; am++)
#pragma unroll
        for (int na = 0; na < 8; na++)
#pragma unroll
            for (int q = 0; q < 4; q++) acc[am][na][q] = 0.f;

#pragma unroll
    for (int it = 0; it < 4; it++) {
        int idx = it * 256 + tid;
        int k   = idx >> 4;
        int c4  = idx & 15;
        float4 v = *reinterpret_cast<const float4*>(W2 + (size_t)k * NCLASS + c4 * 4);
        uint32_t h0 = pkbf2(v.x, v.y), h1 = pkbf2(v.z, v.w);
        __nv_bfloat162 bh0 = *reinterpret_cast<__nv_bfloat162*>(&h0);
        __nv_bfloat162 bh1 = *reinterpret_cast<__nv_bfloat162*>(&h1);
        float2 f0 = __bfloat1622float2(bh0);
        float2 f1 = __bfloat1622float2(bh1);
        uint32_t l0 = pkbf2(v.x - f0.x, v.y - f0.y);
        uint32_t l1 = pkbf2(v.z - f1.x, v.w - f1.y);
        uint32_t off = (uint32_t)k * 144 + c4 * 8;
        *reinterpret_cast<uint2*>(smc + GM_BHI + off) = make_uint2(h0, h1);
        *reinterpret_cast<uint2*>(smc + GM_BLO + off) = make_uint2(l0, l1);
    }
    __syncthreads();

#pragma unroll
    for (int s = 0; s < 4; s++) {
        uint32_t bh[8][2], bl[8][2];
#pragma unroll
        for (int p = 0; p < 4; p++) {
            uint32_t r4[4];
            ldsm_x4_t(r4, sb + GM_BHI + s * 2304 + p * 32 + boff);
            bh[2 * p][0] = r4[0]; bh[2 * p][1] = r4[1];
            bh[2 * p + 1][0] = r4[2]; bh[2 * p + 1][1] = r4[3];
            ldsm_x4_t(r4, sb + GM_BLO + s * 2304 + p * 32 + boff);
            bl[2 * p][0] = r4[0]; bl[2 * p][1] = r4[1];
            bl[2 * p + 1][0] = r4[2]; bl[2 * p + 1][1] = r4[3];
        }
#pragma unroll
        for (int na = 0; na < 8; na++) {
            mma_bf16(acc[0][na], a2h[0][s], bh[na]);
            mma_bf16(acc[1][na], a2h[1][s], bh[na]);
            mma_bf16(acc[0][na], a2l[0][s], bh[na]);
            mma_bf16(acc[1][na], a2l[1][s], bh[na]);
            mma_bf16(acc[0][na], a2h[0][s], bl[na]);
            mma_bf16(acc[1][na], a2h[1][s], bl[na]);
        }
    }

    // store z0 (fp32) + y0 (fp16, fused cast)
#pragma unroll
    for (int am = 0; am < 2; am++) {
        int r0 = bm + wr + am * 16 + (l >> 2);
        int col = (l & 3) * 2;
#pragma unroll
        for (int na = 0; na < 8; na++) {
            if (r0 < n) {
                *reinterpret_cast<float2*>(Z0 + (size_t)r0 * NCLASS + na * 8 + col) =
                    make_float2(acc[am][na][0], acc[am][na][1]);
                __half2 hh = __floats2half2_rn(acc[am][na][0], acc[am][na][1]);
                *reinterpret_cast<__half2*>(Y0 + (size_t)r0 * NCLASS + na * 8 + col) = hh;
            }
            if (r0 + 8 < n) {
                *reinterpret_cast<float2*>(Z0 + (size_t)(r0 + 8) * NCLASS + na * 8 + col) =
                    make_float2(acc[am][na][2], acc[am][na][3]);
                __half2 hh = __floats2half2_rn(acc[am][na][2], acc[am][na][3]);
                *reinterpret_cast<__half2*>(Y0 + (size_t)(r0 + 8) * NCLASS + na * 8 + col) = hh;
            }
        }
    }
}

// =================================================================
// CSR construction (3-kernel scan — proven ~12us)
// =================================================================
__global__ __launch_bounds__(256) void hist_dst(
    const int* __restrict__ dst, int* __restrict__ cnt, int e)
{
    int i = blockIdx.x * 256 + threadIdx.x;
    if (i < e) atomicAdd(&cnt[dst[i]], 1);
}

// scan1 also bins degrees (fused deg_hist)
__global__ __launch_bounds__(SCAN_BLK) void scan1(
    const int* __restrict__ cnt, int* __restrict__ rowptr,
    int* __restrict__ bsums, int* __restrict__ dbin, int n)
{
    __shared__ int sh[SCAN_BLK];
    int t = threadIdx.x;
    int i = blockIdx.x * SCAN_BLK + t;
    int v = (i < n) ? cnt[i] : 0;
    if (i < n) {
        int d = v > 255 ? 255 : v;
        atomicAdd(&dbin[d], 1);
    }
    sh[t] = v;
    __syncthreads();
#pragma unroll
    for (int off = 1; off < SCAN_BLK; off <<= 1) {
        int x = (t >= off) ? sh[t - off] : 0;
        __syncthreads();
        sh[t] += x;
        __syncthreads();
    }
    int incl = sh[t];
    if (i < n) rowptr[i] = incl - v;
    if (t == SCAN_BLK - 1) bsums[blockIdx.x] = incl;
}

__global__ __launch_bounds__(128) void scan2(int* __restrict__ bsums, int nb)
{
    __shared__ int sh[128];
    int t = threadIdx.x;
    int v = (t < nb) ? bsums[t] : 0;
    sh[t] = v;
    __syncthreads();
#pragma unroll
    for (int off = 1; off < 128; off <<= 1) {
        int x = (t >= off) ? sh[t - off] : 0;
        __syncthreads();
        sh[t] += x;
        __syncthreads();
    }
    if (t < nb) bsums[t] = sh[t] - v;
}

__global__ __launch_bounds__(256) void scan3(
    int* __restrict__ rowptr, int* __restrict__ cursor,
    const int* __restrict__ bsums, int n, int e)
{
    int i = blockIdx.x * 256 + threadIdx.x;
    if (i < n) {
        int v = rowptr[i] + bsums[i >> 10];
        rowptr[i] = v;
        cursor[i] = v;
    }
    if (i == n) rowptr[n] = e;
}

// pack: src (17 bits, <<15) | weight q15 (15 bits)
__global__ __launch_bounds__(256) void build_edges(
    const int* __restrict__ src, const int* __restrict__ dst,
    const float* __restrict__ ew, int* __restrict__ cursor,
    uint32_t* __restrict__ edges, int e)
{
    int i = blockIdx.x * 256 + threadIdx.x;
    if (i < e) {
        int d = dst[i];
        int pos = atomicAdd(&cursor[d], 1);
        int q = __float2int_rn(ew[i] * 32768.0f);
        if (q > 32767) q = 32767;
        if (q < 0) q = 0;
        edges[pos] = ((uint32_t)src[i] << 15) | (uint32_t)q;
    }
}

// exclusive scan over REVERSED bins -> descending-degree offsets
__global__ __launch_bounds__(256) void scan_bins(int* __restrict__ dbin)
{
    __shared__ int sh[256];
    int t = threadIdx.x;
    int v = dbin[255 - t];
    sh[t] = v;
    __syncthreads();
#pragma unroll
    for (int off = 1; off < 256; off <<= 1) {
        int x = (t >= off) ? sh[t - off] : 0;
        __syncthreads();
        sh[t] += x;
        __syncthreads();
    }
    dbin[255 - t] = sh[t] - v;
}

__global__ __launch_bounds__(256) void perm_scatter(
    const int* __restrict__ rowptr, int* __restrict__ dbin,
    int* __restrict__ perm, int n)
{
    int i = blockIdx.x * 256 + threadIdx.x;
    if (i < n) {
        int deg = rowptr[i + 1] - rowptr[i];
        if (deg > 255) deg = 255;
        int pos = atomicAdd(&dbin[deg], 1);
        perm[pos] = i;
    }
}

// =================================================================
// gather: FOUR nodes per warp (8 lanes each) via degree-sorted perm.
// Injection hoisted: acc init = ratio * inj_row (fp16 y0),
// o = c1 * acc. 2-deep unroll; packed 4B edges.
// =================================================================
__device__ __forceinline__ void load_row8_h(
    const __half* zin, uint32_t node, int c8, float* v)
{
    float4 raw = __ldg(reinterpret_cast<const float4*>(zin + (size_t)node * NCLASS) + c8);
    const __half2* h = reinterpret_cast<const __half2*>(&raw);
#pragma unroll
    for (int j = 0; j < 4; j++) {
        float2 f = __half22float2(h[j]);
        v[2 * j]     = f.x;
        v[2 * j + 1] = f.y;
    }
}

#define WQ 3.0517578125e-5f   // 1/32768

template<bool LAST>
__global__ __launch_bounds__(256) void gather_nodes(
    const uint32_t* __restrict__ edges, const int* __restrict__ rowptr,
    const int* __restrict__ perm,
    const __half* __restrict__ zin, const __half* __restrict__ inj,
    void* __restrict__ zout_v, float c1, float ratio, int n)
{
    int lane = threadIdx.x & 31;
    int warp = (blockIdx.x * 256 + threadIdx.x) >> 5;
    int pidx = warp * 4 + (lane >> 3);   // 4 permutation slots per warp
    int c8   = lane & 7;

    bool valid = (pidx < n);
    int node = valid ? __ldg(&perm[pidx]) : 0;
    int beg = 0, end = 0;
    if (valid) {
        beg = __ldg(&rowptr[node]);
        end = __ldg(&rowptr[node + 1]);
    }

    // hoisted injection: acc = ratio * inj_row (load overlaps edge loop)
    float acc[8];
    {
        float iv[8];
        load_row8_h(inj, (uint32_t)node, c8, iv);
#pragma unroll
        for (int j = 0; j < 8; j++) acc[j] = ratio * iv[j];
    }

    int i = beg;
    for (; i + 1 < end; i += 2) {
        uint32_t e0 = __ldg(&edges[i]);
        uint32_t e1 = __ldg(&edges[i + 1]);
        float v0[8], v1[8];
        load_row8_h(zin, e0 >> 15, c8, v0);
        load_row8_h(zin, e1 >> 15, c8, v1);
        float w0 = (float)(e0 & 0x7FFFu) * WQ;
        float w1 = (float)(e1 & 0x7FFFu) * WQ;
#pragma unroll
        for (int j = 0; j < 8; j++) acc[j] = fmaf(w0, v0[j], acc[j]);
#pragma unroll
        for (int j = 0; j < 8; j++) acc[j] = fmaf(w1, v1[j], acc[j]);
    }
    if (i < end) {
        uint32_t e0 = __ldg(&edges[i]);
        float v0[8];
        load_row8_h(zin, e0 >> 15, c8, v0);
        float w0 = (float)(e0 & 0x7FFFu) * WQ;
#pragma unroll
        for (int j = 0; j < 8; j++) acc[j] = fmaf(w0, v0[j], acc[j]);
    }

    float o[8];
#pragma unroll
    for (int j = 0; j < 8; j++) o[j] = c1 * acc[j];

    if (!LAST) {
        if (valid) {
            __half2 h[4];
#pragma unroll
            for (int j = 0; j < 4; j++)
                h[j] = __floats2half2_rn(o[2 * j], o[2 * j + 1]);
            __half* zo = (__half*)zout_v;
            *(reinterpret_cast<float4*>(zo + (size_t)node * NCLASS) + c8) =
                *reinterpret_cast<float4*>(h);
        }
    } else {
        const unsigned FULL = 0xFFFFFFFFu;
        float m = o[0];
#pragma unroll
        for (int j = 1; j < 8; j++) m = fmaxf(m, o[j]);
#pragma unroll
        for (int off = 1; off < 8; off <<= 1)
            m = fmaxf(m, __shfl_xor_sync(FULL, m, off));
        float s = 0.f;
#pragma unroll
        for (int j = 0; j < 8; j++) s += __expf(o[j] - m);
#pragma unroll
        for (int off = 1; off < 8; off <<= 1)
            s += __shfl_xor_sync(FULL, s, off);
        float l = m + __logf(s);
        if (valid) {
            float* zo = (float*)zout_v;
            float4 r0 = make_float4(o[0] - l, o[1] - l, o[2] - l, o[3] - l);
            float4 r1 = make_float4(o[4] - l, o[5] - l, o[6] - l, o[7] - l);
            float4* p = reinterpret_cast<float4*>(zo + (size_t)node * NCLASS);
            p[2 * c8]     = r0;
            p[2 * c8 + 1] = r1;
        }
    }
}

// =================================================================
// launch
// =================================================================
extern "C" void kernel_launch(void* const* d_in, const int* in_sizes, int n_in,
                              void* d_out, int out_size)
{
    const float* x   = (const float*)d_in[0];
    const int*   ei  = (const int*)  d_in[1];
    const float* ew  = (const float*)d_in[2];
    const float* W1  = (const float*)d_in[3];
    const float* W2  = (const float*)d_in[4];
    float*       out = (float*)d_out;

    const int n = in_sizes[0] / NFEAT;
    const int e = in_sizes[2];
    const int* src = ei;
    const int* dst = ei + e;

    float*    z0  = nullptr; cudaGetSymbolAddress((void**)&z0,  g_z0);
    __half*   y0  = nullptr; cudaGetSymbolAddress((void**)&y0,  g_y0);
    __half*   ya  = nullptr; cudaGetSymbolAddress((void**)&ya,  g_ya);
    __half*   yb  = nullptr; cudaGetSymbolAddress((void**)&yb,  g_yb);
    int*      rp  = nullptr; cudaGetSymbolAddress((void**)&rp,  g_rowptr);
    int*      cur = nullptr; cudaGetSymbolAddress((void**)&cur, g_cursor);
    int*      bs  = nullptr; cudaGetSymbolAddress((void**)&bs,  g_bsums);
    int*      db  = nullptr; cudaGetSymbolAddress((void**)&db,  g_dbin);
    int*      pm  = nullptr; cudaGetSymbolAddress((void**)&pm,  g_perm);
    uint32_t* edg = nullptr; cudaGetSymbolAddress((void**)&edg, g_edges);

    static cudaStream_t sG = nullptr;
    static cudaEvent_t  evF = nullptr, evG = nullptr;
    if (sG == nullptr) {
        cudaStreamCreateWithFlags(&sG, cudaStreamNonBlocking);
        cudaEventCreateWithFlags(&evF, cudaEventDisableTiming);
        cudaEventCreateWithFlags(&evG, cudaEventDisableTiming);
        cudaFuncSetAttribute(gemm_mma,
            cudaFuncAttributeMaxDynamicSharedMemorySize, GM_SMEM);
    }

    // ---- fork: tensor-core GEMM (with fused fp16 cast) on side stream ----
    cudaEventRecord(evF, 0);
    cudaStreamWaitEvent(sG, evF, 0);
    gemm_mma<<<(n + 255) / 256, 256, GM_SMEM, sG>>>(x, W1, W2, z0, y0, n);
    cudaEventRecord(evG, sG);

    // ---- CSR build + degree-sorted perm on capture stream ----
    cudaMemsetAsync(cur, 0, (size_t)n * sizeof(int), 0);
    cudaMemsetAsync(db, 0, 256 * sizeof(int), 0);
    hist_dst<<<(e + 255) / 256, 256>>>(dst, cur, e);
    int nb = (n + SCAN_BLK - 1) / SCAN_BLK;
    scan1<<<nb, SCAN_BLK>>>(cur, rp, bs, db, n);
    scan_bins<<<1, 256>>>(db);
    scan2<<<1, 128>>>(bs, nb);
    scan3<<<(n + 256) / 256, 256>>>(rp, cur, bs, n, e);
    build_edges<<<(e + 255) / 256, 256>>>(src, dst, ew, cur, edg, e);
    perm_scatter<<<(n + 255) / 256, 256>>>(rp, db, pm, n);

    // ---- join ----
    cudaStreamWaitEvent(0, evG, 0);

    // ---- APPNP, scaled-fp16 pipeline ----
    // y_t = z_t / 16^t; injection hoisted: ratio_t = ALPHA / 16^(t-1)
    const float S = 16.0f;
    const int gblocks = (n * 8 + 255) / 256;   // 4 nodes per warp

    // iter 0 (t=1): y0 -> y1 (ya); ratio = ALPHA
    gather_nodes<false><<<gblocks, 256>>>(
        edg, rp, pm, y0, y0, ya, 1.0f / S, ALPHA, n);

    // iters 1..8 (t=2..9): y_t -> y_{t+1}
    __half* bufs[2] = { ya, yb };
    float ratio = ALPHA / S;
    for (int t = 1; t <= 8; t++) {
        __half* zin  = bufs[(t + 1) & 1];
        __half* zout = bufs[t & 1];
        gather_nodes<false><<<gblocks, 256>>>(
            edg, rp, pm, zin, y0, zout, 1.0f / S, ratio, n);
        ratio /= S;
    }

    // final (t=10): input y9 = bufs[0]; o = S9 * acc; fused log_softmax
    float S9 = 1.0f;
    for (int k = 0; k < 9; k++) S9 *= S;
    gather_nodes<true><<<gblocks, 256>>>(
        edg, rp, pm, bufs[0], y0, out, S9, ALPHA / S9, n);
}

// round 17
// speedup vs baseline: 1.4309x; 1.0053x over previous
#include <cuda_runtime.h>
#include <cuda_fp16.h>
#include <cuda_bf16.h>
#include <cstdint>

// ---------------- problem constants ----------------
#define MAXN    100000
#define MAXE    3200000
#define NFEAT   512
#define HID     64
#define NCLASS  64
#define ALPHA   0.1f
#define NITER   10
#define SCAN_BLK 1024

// ---------------- static device scratch ----------------
__device__ float    g_z0[MAXN * NCLASS];   // fp32 base prediction
__device__ __half   g_y0[MAXN * NCLASS];   // fp16 cast of z0
__device__ __half   g_ya[MAXN * NCLASS];   // fp16 scaled z ping
__device__ __half   g_yb[MAXN * NCLASS];   // fp16 scaled z pong
__device__ int      g_rowptr[MAXN + 1];
__device__ int      g_cursor[MAXN];
__device__ int      g_bsums[128];
__device__ int      g_dbin[256];           // degree histogram bins
__device__ int      g_perm[MAXN];          // degree-sorted node permutation
__device__ uint32_t g_edges[MAXE];         // packed: src(17b) << 15 | w_q15(15b)

// ================= mma.sync helpers (baseline sm_80+, works on sm_103) ====
__device__ __forceinline__ uint32_t smem_u32(const void* p) {
    uint32_t a;
    asm("{ .reg .u64 t; cvta.to.shared.u64 t, %1; cvt.u32.u64 %0, t; }"
        : "=r"(a) : "l"(p));
    return a;
}
__device__ __forceinline__ void ldsm_x4(uint32_t* r, uint32_t addr) {
    asm volatile("ldmatrix.sync.aligned.m8n8.x4.shared.b16 {%0,%1,%2,%3}, [%4];"
                 : "=r"(r[0]), "=r"(r[1]), "=r"(r[2]), "=r"(r[3]) : "r"(addr));
}
__device__ __forceinline__ void ldsm_x4_t(uint32_t* r, uint32_t addr) {
    asm volatile("ldmatrix.sync.aligned.m8n8.x4.trans.shared.b16 {%0,%1,%2,%3}, [%4];"
                 : "=r"(r[0]), "=r"(r[1]), "=r"(r[2]), "=r"(r[3]) : "r"(addr));
}
__device__ __forceinline__ void mma_bf16(
    float* d, const uint32_t* a, const uint32_t* b)
{
    asm volatile(
        "mma.sync.aligned.m16n8k16.row.col.f32.bf16.bf16.f32 "
        "{%0,%1,%2,%3}, {%4,%5,%6,%7}, {%8,%9}, {%0,%1,%2,%3};"
        : "+f"(d[0]), "+f"(d[1]), "+f"(d[2]), "+f"(d[3])
        : "r"(a[0]), "r"(a[1]), "r"(a[2]), "r"(a[3]), "r"(b[0]), "r"(b[1]));
}
__device__ __forceinline__ uint32_t pkbf2(float a, float b) {
    __nv_bfloat162 h = __floats2bfloat162_rn(a, b);
    return *reinterpret_cast<uint32_t*>(&h);
}

// =================================================================
// mma.sync fused GEMM: z0 = relu(x @ W1) @ W2, bf16 hi/lo 3-term split.
// Epilogue also emits y0 = fp16(z0) (fused cvt).
// =================================================================
#define GM_AHI 0
#define GM_ALO 36864
#define GM_BHI 73728
#define GM_BLO 82944
#define GM_SMEM 92160

__global__ __launch_bounds__(256) void gemm_mma(
    const float* __restrict__ X, const float* __restrict__ W1,
    const float* __restrict__ W2, float* __restrict__ Z0,
    __half* __restrict__ Y0, int n)
{
    extern __shared__ char smc[];
    const uint32_t sb = smem_u32(smc);
    const int tid = threadIdx.x;
    const int wid = tid >> 5;
    const int l   = tid & 31;
    const int bm  = blockIdx.x * 256;
    const int wr  = wid * 32;

    const int arow = (l & 7) + ((l >> 3) & 1) * 8;
    const uint32_t akb = ((l >> 4) & 1) * 16;
    const uint32_t aoff0 = (uint32_t)(wr + arow) * 144 + akb;
    const uint32_t aoff1 = (uint32_t)(wr + 16 + arow) * 144 + akb;
    const uint32_t boff  = (uint32_t)arow * 144 + akb;

    float acc[2][8][4];
#pragma unroll
    for (int am = 0; am < 2; am++)
#pragma unroll
        for (int na = 0; na < 8; na++)
#pragma unroll
            for (int q = 0; q < 4; q++) acc[am][na][q] = 0.f;

    for (int c = 0; c < 8; c++) {
#pragma unroll
        for (int it = 0; it < 16; it++) {
            int idx = it * 256 + tid;
            int r   = idx >> 4;
            int c4  = idx & 15;
            int row = bm + r;
            float4 v = make_float4(0.f, 0.f, 0.f, 0.f);
            if (row < n)
                v = *reinterpret_cast<const float4*>(X + (size_t)row * NFEAT + c * 64 + c4 * 4);
            uint32_t h0 = pkbf2(v.x, v.y), h1 = pkbf2(v.z, v.w);
            __nv_bfloat162 bh0 = *reinterpret_cast<__nv_bfloat162*>(&h0);
            __nv_bfloat162 bh1 = *reinterpret_cast<__nv_bfloat162*>(&h1);
            float2 f0 = __bfloat1622float2(bh0);
            float2 f1 = __bfloat1622float2(bh1);
            uint32_t l0 = pkbf2(v.x - f0.x, v.y - f0.y);
            uint32_t l1 = pkbf2(v.z - f1.x, v.w - f1.y);
            uint32_t off = (uint32_t)r * 144 + c4 * 8;
            *reinterpret_cast<uint2*>(smc + GM_AHI + off) = make_uint2(h0, h1);
            *reinterpret_cast<uint2*>(smc + GM_ALO + off) = make_uint2(l0, l1);
        }
#pragma unroll
        for (int it = 0; it < 4; it++) {
            int idx = it * 256 + tid;
            int k   = idx >> 4;
            int c4  = idx & 15;
            float4 v = *reinterpret_cast<const float4*>(W1 + (size_t)(c * 64 + k) * HID + c4 * 4);
            uint32_t h0 = pkbf2(v.x, v.y), h1 = pkbf2(v.z, v.w);
            __nv_bfloat162 bh0 = *reinterpret_cast<__nv_bfloat162*>(&h0);
            __nv_bfloat162 bh1 = *reinterpret_cast<__nv_bfloat162*>(&h1);
            float2 f0 = __bfloat1622float2(bh0);
            float2 f1 = __bfloat1622float2(bh1);
            uint32_t l0 = pkbf2(v.x - f0.x, v.y - f0.y);
            uint32_t l1 = pkbf2(v.z - f1.x, v.w - f1.y);
            uint32_t off = (uint32_t)k * 144 + c4 * 8;
            *reinterpret_cast<uint2*>(smc + GM_BHI + off) = make_uint2(h0, h1);
            *reinterpret_cast<uint2*>(smc + GM_BLO + off) = make_uint2(l0, l1);
        }
        __syncthreads();

#pragma unroll
        for (int s = 0; s < 4; s++) {
            uint32_t ah0[4], ah1[4], al0[4], al1[4];
            ldsm_x4(ah0, sb + GM_AHI + aoff0 + s * 32);
            ldsm_x4(ah1, sb + GM_AHI + aoff1 + s * 32);
            ldsm_x4(al0, sb + GM_ALO + aoff0 + s * 32);
            ldsm_x4(al1, sb + GM_ALO + aoff1 + s * 32);
            uint32_t bh[8][2], bl[8][2];
#pragma unroll
            for (int p = 0; p < 4; p++) {
                uint32_t r4[4];
                ldsm_x4_t(r4, sb + GM_BHI + s * 2304 + p * 32 + boff);
                bh[2 * p][0] = r4[0]; bh[2 * p][1] = r4[1];
                bh[2 * p + 1][0] = r4[2]; bh[2 * p + 1][1] = r4[3];
                ldsm_x4_t(r4, sb + GM_BLO + s * 2304 + p * 32 + boff);
                bl[2 * p][0] = r4[0]; bl[2 * p][1] = r4[1];
                bl[2 * p + 1][0] = r4[2]; bl[2 * p + 1][1] = r4[3];
            }
#pragma unroll
            for (int na = 0; na < 8; na++) {
                mma_bf16(acc[0][na], ah0, bh[na]);
                mma_bf16(acc[1][na], ah1, bh[na]);
                mma_bf16(acc[0][na], al0, bh[na]);
                mma_bf16(acc[1][na], al1, bh[na]);
                mma_bf16(acc[0][na], ah0, bl[na]);
                mma_bf16(acc[1][na], ah1, bl[na]);
            }
        }
        __syncthreads();
    }

    // ---- phase 2 ----
    uint32_t a2h[2][4][4], a2l[2][4][4];
#pragma unroll
    for (int am = 0; am < 2; am++)
#pragma unroll
        for (int s = 0; s < 4; s++) {
            float v00 = fmaxf(acc[am][2 * s][0], 0.f);
            float v01 = fmaxf(acc[am][2 * s][1], 0.f);
            float v02 = fmaxf(acc[am][2 * s][2], 0.f);
            float v03 = fmaxf(acc[am][2 * s][3], 0.f);
            float v10 = fmaxf(acc[am][2 * s + 1][0], 0.f);
            float v11 = fmaxf(acc[am][2 * s + 1][1], 0.f);
            float v12 = fmaxf(acc[am][2 * s + 1][2], 0.f);
            float v13 = fmaxf(acc[am][2 * s + 1][3], 0.f);
            uint32_t h;
            h = pkbf2(v00, v01); a2h[am][s][0] = h;
            { __nv_bfloat162 b = *reinterpret_cast<__nv_bfloat162*>(&h); float2 f = __bfloat1622float2(b);
              a2l[am][s][0] = pkbf2(v00 - f.x, v01 - f.y); }
            h = pkbf2(v02, v03); a2h[am][s][1] = h;
            { __nv_bfloat162 b = *reinterpret_cast<__nv_bfloat162*>(&h); float2 f = __bfloat1622float2(b);
              a2l[am][s][1] = pkbf2(v02 - f.x, v03 - f.y); }
            h = pkbf2(v10, v11); a2h[am][s][2] = h;
            { __nv_bfloat162 b = *reinterpret_cast<__nv_bfloat162*>(&h); float2 f = __bfloat1622float2(b);
              a2l[am][s][2] = pkbf2(v10 - f.x, v11 - f.y); }
            h = pkbf2(v12, v13); a2h[am][s][3] = h;
            { __nv_bfloat162 b = *reinterpret_cast<__nv_bfloat162*>(&h); float2 f = __bfloat1622float2(b);
              a2l[am][s][3] = pkbf2(v12 - f.x, v13 - f.y); }
        }

#pragma unroll
    for (int am = 0; am < 2; am++)
#pragma unroll
        for (int na = 0; na < 8; na++)
#pragma unroll
            for (int q = 0; q < 4; q++) acc[am][na][q] = 0.f;

#pragma unroll
    for (int it = 0; it < 4; it++) {
        int idx = it * 256 + tid;
        int k   = idx >> 4;
        int c4  = idx & 15;
        float4 v = *reinterpret_cast<const float4*>(W2 + (size_t)k * NCLASS + c4 * 4);
        uint32_t h0 = pkbf2(v.x, v.y), h1 = pkbf2(v.z, v.w);
        __nv_bfloat162 bh0 = *reinterpret_cast<__nv_bfloat162*>(&h0);
        __nv_bfloat162 bh1 = *reinterpret_cast<__nv_bfloat162*>(&h1);
        float2 f0 = __bfloat1622float2(bh0);
        float2 f1 = __bfloat1622float2(bh1);
        uint32_t l0 = pkbf2(v.x - f0.x, v.y - f0.y);
        uint32_t l1 = pkbf2(v.z - f1.x, v.w - f1.y);
        uint32_t off = (uint32_t)k * 144 + c4 * 8;
        *reinterpret_cast<uint2*>(smc + GM_BHI + off) = make_uint2(h0, h1);
        *reinterpret_cast<uint2*>(smc + GM_BLO + off) = make_uint2(l0, l1);
    }
    __syncthreads();

#pragma unroll
    for (int s = 0; s < 4; s++) {
        uint32_t bh[8][2], bl[8][2];
#pragma unroll
        for (int p = 0; p < 4; p++) {
            uint32_t r4[4];
            ldsm_x4_t(r4, sb + GM_BHI + s * 2304 + p * 32 + boff);
            bh[2 * p][0] = r4[0]; bh[2 * p][1] = r4[1];
            bh[2 * p + 1][0] = r4[2]; bh[2 * p + 1][1] = r4[3];
            ldsm_x4_t(r4, sb + GM_BLO + s * 2304 + p * 32 + boff);
            bl[2 * p][0] = r4[0]; bl[2 * p][1] = r4[1];
            bl[2 * p + 1][0] = r4[2]; bl[2 * p + 1][1] = r4[3];
        }
#pragma unroll
        for (int na = 0; na < 8; na++) {
            mma_bf16(acc[0][na], a2h[0][s], bh[na]);
            mma_bf16(acc[1][na], a2h[1][s], bh[na]);
            mma_bf16(acc[0][na], a2l[0][s], bh[na]);
            mma_bf16(acc[1][na], a2l[1][s], bh[na]);
            mma_bf16(acc[0][na], a2h[0][s], bl[na]);
            mma_bf16(acc[1][na], a2h[1][s], bl[na]);
        }
    }

    // store z0 (fp32) + y0 (fp16, fused cast)
#pragma unroll
    for (int am = 0; am < 2; am++) {
        int r0 = bm + wr + am * 16 + (l >> 2);
        int col = (l & 3) * 2;
#pragma unroll
        for (int na = 0; na < 8; na++) {
            if (r0 < n) {
                *reinterpret_cast<float2*>(Z0 + (size_t)r0 * NCLASS + na * 8 + col) =
                    make_float2(acc[am][na][0], acc[am][na][1]);
                __half2 hh = __floats2half2_rn(acc[am][na][0], acc[am][na][1]);
                *reinterpret_cast<__half2*>(Y0 + (size_t)r0 * NCLASS + na * 8 + col) = hh;
            }
            if (r0 + 8 < n) {
                *reinterpret_cast<float2*>(Z0 + (size_t)(r0 + 8) * NCLASS + na * 8 + col) =
                    make_float2(acc[am][na][2], acc[am][na][3]);
                __half2 hh = __floats2half2_rn(acc[am][na][2], acc[am][na][3]);
                *reinterpret_cast<__half2*>(Y0 + (size_t)(r0 + 8) * NCLASS + na * 8 + col) = hh;
            }
        }
    }
}

// =================================================================
// CSR construction
// =================================================================
__global__ __launch_bounds__(256) void hist_dst(
    const int* __restrict__ dst, int* __restrict__ cnt, int e)
{
    int i = blockIdx.x * 256 + threadIdx.x;
    if (i < e) atomicAdd(&cnt[dst[i]], 1);
}

// scan1 also bins degrees (fused deg_hist)
__global__ __launch_bounds__(SCAN_BLK) void scan1(
    const int* __restrict__ cnt, int* __restrict__ rowptr,
    int* __restrict__ bsums, int* __restrict__ dbin, int n)
{
    __shared__ int sh[SCAN_BLK];
    int t = threadIdx.x;
    int i = blockIdx.x * SCAN_BLK + t;
    int v = (i < n) ? cnt[i] : 0;
    if (i < n) {
        int d = v > 255 ? 255 : v;
        atomicAdd(&dbin[d], 1);
    }
    sh[t] = v;
    __syncthreads();
#pragma unroll
    for (int off = 1; off < SCAN_BLK; off <<= 1) {
        int x = (t >= off) ? sh[t - off] : 0;
        __syncthreads();
        sh[t] += x;
        __syncthreads();
    }
    int incl = sh[t];
    if (i < n) rowptr[i] = incl - v;
    if (t == SCAN_BLK - 1) bsums[blockIdx.x] = incl;
}

// merged: block 0 scans dbin (reversed -> descending-degree offsets),
//         block 1 scans bsums (exclusive).
__global__ __launch_bounds__(256) void scan_ab(
    int* __restrict__ dbin, int* __restrict__ bsums, int nb)
{
    __shared__ int sh[256];
    int t = threadIdx.x;
    if (blockIdx.x == 0) {
        int v = dbin[255 - t];
        sh[t] = v;
        __syncthreads();
#pragma unroll
        for (int off = 1; off < 256; off <<= 1) {
            int x = (t >= off) ? sh[t - off] : 0;
            __syncthreads();
            sh[t] += x;
            __syncthreads();
        }
        dbin[255 - t] = sh[t] - v;
    } else {
        int v = (t < nb) ? bsums[t] : 0;
        sh[t] = v;
        __syncthreads();
#pragma unroll
        for (int off = 1; off < 256; off <<= 1) {
            int x = (t >= off) ? sh[t - off] : 0;
            __syncthreads();
            sh[t] += x;
            __syncthreads();
        }
        if (t < nb) bsums[t] = sh[t] - v;
    }
}

// scan3 + perm_scatter fused: cursor[] still holds raw degrees here,
// so read degree, scatter into perm via dbin offsets, then overwrite
// rowptr/cursor with global offsets.
__global__ __launch_bounds__(256) void scan3_perm(
    int* __restrict__ rowptr, int* __restrict__ cursor,
    const int* __restrict__ bsums, int* __restrict__ dbin,
    int* __restrict__ perm, int n, int e)
{
    int i = blockIdx.x * 256 + threadIdx.x;
    if (i < n) {
        int deg = cursor[i];                 // raw degree (pre-overwrite)
        int d = deg > 255 ? 255 : deg;
        int pos = atomicAdd(&dbin[d], 1);
        perm[pos] = i;
        int v = rowptr[i] + bsums[i >> 10];
        rowptr[i] = v;
        cursor[i] = v;
    }
    if (i == n) rowptr[n] = e;
}

// pack: src (17 bits, <<15) | weight q15 (15 bits)
__global__ __launch_bounds__(256) void build_edges(
    const int* __restrict__ src, const int* __restrict__ dst,
    const float* __restrict__ ew, int* __restrict__ cursor,
    uint32_t* __restrict__ edges, int e)
{
    int i = blockIdx.x * 256 + threadIdx.x;
    if (i < e) {
        int d = dst[i];
        int pos = atomicAdd(&cursor[d], 1);
        int q = __float2int_rn(ew[i] * 32768.0f);
        if (q > 32767) q = 32767;
        if (q < 0) q = 0;
        edges[pos] = ((uint32_t)src[i] << 15) | (uint32_t)q;
    }
}

// =================================================================
// gather: FOUR nodes per warp (8 lanes each) via degree-sorted perm.
// Injection hoisted into accumulator init. 2-deep unroll; 4B edges.
// =================================================================
__device__ __forceinline__ void load_row8_h(
    const __half* zin, uint32_t node, int c8, float* v)
{
    float4 raw = __ldg(reinterpret_cast<const float4*>(zin + (size_t)node * NCLASS) + c8);
    const __half2* h = reinterpret_cast<const __half2*>(&raw);
#pragma unroll
    for (int j = 0; j < 4; j++) {
        float2 f = __half22float2(h[j]);
        v[2 * j]     = f.x;
        v[2 * j + 1] = f.y;
    }
}

#define WQ 3.0517578125e-5f   // 1/32768

template<bool LAST>
__global__ __launch_bounds__(256) void gather_nodes(
    const uint32_t* __restrict__ edges, const int* __restrict__ rowptr,
    const int* __restrict__ perm,
    const __half* __restrict__ zin, const __half* __restrict__ inj,
    void* __restrict__ zout_v, float c1, float ratio, int n)
{
    int lane = threadIdx.x & 31;
    int warp = (blockIdx.x * 256 + threadIdx.x) >> 5;
    int pidx = warp * 4 + (lane >> 3);
    int c8   = lane & 7;

    bool valid = (pidx < n);
    int node = valid ? __ldg(&perm[pidx]) : 0;
    int beg = 0, end = 0;
    if (valid) {
        beg = __ldg(&rowptr[node]);
        end = __ldg(&rowptr[node + 1]);
    }

    float acc[8];
    {
        float iv[8];
        load_row8_h(inj, (uint32_t)node, c8, iv);
#pragma unroll
        for (int j = 0; j < 8; j++) acc[j] = ratio * iv[j];
    }

    int i = beg;
    for (; i + 1 < end; i += 2) {
        uint32_t e0 = __ldg(&edges[i]);
        uint32_t e1 = __ldg(&edges[i + 1]);
        float v0[8], v1[8];
        load_row8_h(zin, e0 >> 15, c8, v0);
        load_row8_h(zin, e1 >> 15, c8, v1);
        float w0 = (float)(e0 & 0x7FFFu) * WQ;
        float w1 = (float)(e1 & 0x7FFFu) * WQ;
#pragma unroll
        for (int j = 0; j < 8; j++) acc[j] = fmaf(w0, v0[j], acc[j]);
#pragma unroll
        for (int j = 0; j < 8; j++) acc[j] = fmaf(w1, v1[j], acc[j]);
    }
    if (i < end) {
        uint32_t e0 = __ldg(&edges[i]);
        float v0[8];
        load_row8_h(zin, e0 >> 15, c8, v0);
        float w0 = (float)(e0 & 0x7FFFu) * WQ;
#pragma unroll
        for (int j = 0; j < 8; j++) acc[j] = fmaf(w0, v0[j], acc[j]);
    }

    float o[8];
#pragma unroll
    for (int j = 0; j < 8; j++) o[j] = c1 * acc[j];

    if (!LAST) {
        if (valid) {
            __half2 h[4];
#pragma unroll
            for (int j = 0; j < 4; j++)
                h[j] = __floats2half2_rn(o[2 * j], o[2 * j + 1]);
            __half* zo = (__half*)zout_v;
            *(reinterpret_cast<float4*>(zo + (size_t)node * NCLASS) + c8) =
                *reinterpret_cast<float4*>(h);
        }
    } else {
        const unsigned FULL = 0xFFFFFFFFu;
        float m = o[0];
#pragma unroll
        for (int j = 1; j < 8; j++) m = fmaxf(m, o[j]);
#pragma unroll
        for (int off = 1; off < 8; off <<= 1)
            m = fmaxf(m, __shfl_xor_sync(FULL, m, off));
        float s = 0.f;
#pragma unroll
        for (int j = 0; j < 8; j++) s += __expf(o[j] - m);
#pragma unroll
        for (int off = 1; off < 8; off <<= 1)
            s += __shfl_xor_sync(FULL, s, off);
        float l = m + __logf(s);
        if (valid) {
            float* zo = (float*)zout_v;
            float4 r0 = make_float4(o[0] - l, o[1] - l, o[2] - l, o[3] - l);
            float4 r1 = make_float4(o[4] - l, o[5] - l, o[6] - l, o[7] - l);
            float4* p = reinterpret_cast<float4*>(zo + (size_t)node * NCLASS);
            p[2 * c8]     = r0;
            p[2 * c8 + 1] = r1;
        }
    }
}

// =================================================================
// launch
// =================================================================
extern "C" void kernel_launch(void* const* d_in, const int* in_sizes, int n_in,
                              void* d_out, int out_size)
{
    const float* x   = (const float*)d_in[0];
    const int*   ei  = (const int*)  d_in[1];
    const float* ew  = (const float*)d_in[2];
    const float* W1  = (const float*)d_in[3];
    const float* W2  = (const float*)d_in[4];
    float*       out = (float*)d_out;

    const int n = in_sizes[0] / NFEAT;
    const int e = in_sizes[2];
    const int* src = ei;
    const int* dst = ei + e;

    float*    z0  = nullptr; cudaGetSymbolAddress((void**)&z0,  g_z0);
    __half*   y0  = nullptr; cudaGetSymbolAddress((void**)&y0,  g_y0);
    __half*   ya  = nullptr; cudaGetSymbolAddress((void**)&ya,  g_ya);
    __half*   yb  = nullptr; cudaGetSymbolAddress((void**)&yb,  g_yb);
    int*      rp  = nullptr; cudaGetSymbolAddress((void**)&rp,  g_rowptr);
    int*      cur = nullptr; cudaGetSymbolAddress((void**)&cur, g_cursor);
    int*      bs  = nullptr; cudaGetSymbolAddress((void**)&bs,  g_bsums);
    int*      db  = nullptr; cudaGetSymbolAddress((void**)&db,  g_dbin);
    int*      pm  = nullptr; cudaGetSymbolAddress((void**)&pm,  g_perm);
    uint32_t* edg = nullptr; cudaGetSymbolAddress((void**)&edg, g_edges);

    static cudaStream_t sG = nullptr;
    static cudaEvent_t  evF = nullptr, evG = nullptr;
    if (sG == nullptr) {
        cudaStreamCreateWithFlags(&sG, cudaStreamNonBlocking);
        cudaEventCreateWithFlags(&evF, cudaEventDisableTiming);
        cudaEventCreateWithFlags(&evG, cudaEventDisableTiming);
        cudaFuncSetAttribute(gemm_mma,
            cudaFuncAttributeMaxDynamicSharedMemorySize, GM_SMEM);
    }

    // ---- fork: tensor-core GEMM (with fused fp16 cast) on side stream ----
    cudaEventRecord(evF, 0);
    cudaStreamWaitEvent(sG, evF, 0);
    gemm_mma<<<(n + 255) / 256, 256, GM_SMEM, sG>>>(x, W1, W2, z0, y0, n);
    cudaEventRecord(evG, sG);

    // ---- CSR build + degree-sorted perm on capture stream ----
    cudaMemsetAsync(cur, 0, (size_t)n * sizeof(int), 0);
    cudaMemsetAsync(db, 0, 256 * sizeof(int), 0);
    hist_dst<<<(e + 255) / 256, 256>>>(dst, cur, e);
    int nb = (n + SCAN_BLK - 1) / SCAN_BLK;
    scan1<<<nb, SCAN_BLK>>>(cur, rp, bs, db, n);
    scan_ab<<<2, 256>>>(db, bs, nb);
    scan3_perm<<<(n + 256) / 256, 256>>>(rp, cur, bs, db, pm, n, e);
    build_edges<<<(e + 255) / 256, 256>>>(src, dst, ew, cur, edg, e);

    // ---- join ----
    cudaStreamWaitEvent(0, evG, 0);

    // ---- APPNP, scaled-fp16 pipeline ----
    const float S = 16.0f;
    const int gblocks = (n * 8 + 255) / 256;   // 4 nodes per warp

    // iter 0 (t=1): y0 -> y1 (ya); ratio = ALPHA
    gather_nodes<false><<<gblocks, 256>>>(
        edg, rp, pm, y0, y0, ya, 1.0f / S, ALPHA, n);

    // iters 1..8 (t=2..9)
    __half* bufs[2] = { ya, yb };
    float ratio = ALPHA / S;
    for (int t = 1; t <= 8; t++) {
        __half* zin  = bufs[(t + 1) & 1];
        __half* zout = bufs[t & 1];
        gather_nodes<false><<<gblocks, 256>>>(
            edg, rp, pm, zin, y0, zout, 1.0f / S, ratio, n);
        ratio /= S;
    }

    // final (t=10): fused log_softmax
    float S9 = 1.0f;
    for (int k = 0; k < 9; k++) S9 *= S;
    gather_nodes<true><<<gblocks, 256>>>(
        edg, rp, pm, bufs[0], y0, out, S9, ALPHA / S9, n);
}